// round 1
// baseline (speedup 1.0000x reference)
#include <cuda_runtime.h>
#include <math.h>

#define DMODEL 1024
#define NH 16
#define DK 64
#define BB 4
#define TT 2048
#define MTOT (BB*TT)   // 8192

// Scratch (alloc-free rule: __device__ globals)
__device__ float g_q[BB*NH*TT*DK];     // 32 MB, (b,h,t,d)
__device__ float g_k[BB*NH*TT*DK];
__device__ float g_v[BB*NH*TT*DK];
__device__ float g_ctx[MTOT*DMODEL];   // 32 MB, (b,t,h*dk)

// ---------------------------------------------------------------------------
// GEMM: Y[m,n] = sum_k A[m,k] * W[n,k] + bias[n]
// MODE 0: fused QKV (N=3072 over Wq|Wk|Wv), scatters into g_q/g_k/g_v head-major
// MODE 1: output projection (A = g_ctx), writes plain row-major to out
// 128x128x16 tile, 256 threads, 8x8 per-thread microtile.
// ---------------------------------------------------------------------------
template<int MODE>
__global__ void __launch_bounds__(256)
gemm_kernel(const float* __restrict__ A,
            const float* __restrict__ W0, const float* __restrict__ W1, const float* __restrict__ W2,
            const float* __restrict__ b0v, const float* __restrict__ b1v, const float* __restrict__ b2v,
            float* __restrict__ out)
{
    __shared__ float As[16][132];
    __shared__ float Bs[16][132];

    const int m0  = blockIdx.y * 128;
    const int n0g = blockIdx.x * 128;

    int which = 0, nn0 = n0g;
    const float* W    = W0;
    const float* bias = b0v;
    if (MODE == 0) {
        which = n0g >> 10;           // tile never straddles (128 | 1024)
        nn0   = n0g & 1023;
        W     = (which == 0) ? W0  : (which == 1 ? W1  : W2);
        bias  = (which == 0) ? b0v : (which == 1 ? b1v : b2v);
    }
    const float* Ap = (MODE == 0) ? A : g_ctx;

    const int tid = threadIdx.x;
    const int ty  = tid >> 4, tx = tid & 15;

    float acc[8][8];
    #pragma unroll
    for (int i = 0; i < 8; i++)
        #pragma unroll
        for (int j = 0; j < 8; j++) acc[i][j] = 0.f;

    for (int k0 = 0; k0 < DMODEL; k0 += 16) {
        #pragma unroll
        for (int it = 0; it < 2; it++) {
            int lin = tid + it * 256;
            int row = lin >> 2;
            int c4  = (lin & 3) << 2;
            float4 av = *(const float4*)&Ap[(size_t)(m0 + row) * DMODEL + k0 + c4];
            As[c4+0][row] = av.x; As[c4+1][row] = av.y;
            As[c4+2][row] = av.z; As[c4+3][row] = av.w;
            float4 wv = *(const float4*)&W[(size_t)(nn0 + row) * DMODEL + k0 + c4];
            Bs[c4+0][row] = wv.x; Bs[c4+1][row] = wv.y;
            Bs[c4+2][row] = wv.z; Bs[c4+3][row] = wv.w;
        }
        __syncthreads();

        #pragma unroll
        for (int kk = 0; kk < 16; kk++) {
            float a[8], bb[8];
            *(float4*)&a[0]  = *(const float4*)&As[kk][ty*8];
            *(float4*)&a[4]  = *(const float4*)&As[kk][ty*8 + 4];
            *(float4*)&bb[0] = *(const float4*)&Bs[kk][tx*8];
            *(float4*)&bb[4] = *(const float4*)&Bs[kk][tx*8 + 4];
            #pragma unroll
            for (int i = 0; i < 8; i++)
                #pragma unroll
                for (int j = 0; j < 8; j++)
                    acc[i][j] += a[i] * bb[j];
        }
        __syncthreads();
    }

    if (MODE == 0) {
        float* dst = (which == 0) ? g_q : (which == 1 ? g_k : g_v);
        #pragma unroll
        for (int i = 0; i < 8; i++) {
            int m = m0 + ty*8 + i;
            int b = m >> 11, t = m & 2047;
            #pragma unroll
            for (int j = 0; j < 8; j++) {
                int nn = nn0 + tx*8 + j;
                int h = nn >> 6, d = nn & 63;
                dst[((size_t)((b*NH + h)*TT + t)) * DK + d] = acc[i][j] + bias[nn];
            }
        }
    } else {
        #pragma unroll
        for (int i = 0; i < 8; i++) {
            int m = m0 + ty*8 + i;
            #pragma unroll
            for (int j = 0; j < 8; j++) {
                int n = nn0 + tx*8 + j;
                out[(size_t)m * DMODEL + n] = acc[i][j] + bias[n];
            }
        }
    }
}

// ---------------------------------------------------------------------------
// Flash attention, causal. One block = (b, h, 64-row q tile). 256 threads,
// 16x16 thread grid, 4x4 microtile. Online softmax with running max/sum.
// ---------------------------------------------------------------------------
__global__ void __launch_bounds__(256)
attn_kernel()
{
    extern __shared__ float sm[];
    float* Qs = sm;                 // 64*64
    float* Ks = Qs + 64*64;         // 64*68 (padded, 16B-aligned rows)
    float* Vs = Ks + 64*68;         // 64*64
    float* Ps = Vs + 64*64;         // 64*64

    const int qt  = 31 - (int)blockIdx.x;   // biggest causal tiles first
    const int h   = blockIdx.y;
    const int b   = blockIdx.z;
    const int tid = threadIdx.x;
    const int ty  = tid >> 4, tx = tid & 15;
    const int r0  = ty * 4, c0 = tx * 4;

    const size_t base = (size_t)(b*NH + h) * TT * DK;
    const float* Qg = g_q + base;
    const float* Kg = g_k + base;
    const float* Vg = g_v + base;

    // Q tile, pre-scaled by 1/sqrt(dk) = 0.125
    #pragma unroll
    for (int it = 0; it < 4; it++) {
        int lin = tid + it * 256;
        int row = lin >> 4;
        int c   = (lin & 15) << 2;
        float4 v = *(const float4*)&Qg[(size_t)(qt*64 + row) * DK + c];
        v.x *= 0.125f; v.y *= 0.125f; v.z *= 0.125f; v.w *= 0.125f;
        *(float4*)&Qs[row*64 + c] = v;
    }

    float m_i[4], l_i[4], acc[4][4];
    #pragma unroll
    for (int i = 0; i < 4; i++) {
        m_i[i] = -1e30f; l_i[i] = 0.f;
        #pragma unroll
        for (int j = 0; j < 4; j++) acc[i][j] = 0.f;
    }

    for (int kt = 0; kt <= qt; kt++) {
        __syncthreads();   // prior-iter Ps/Vs readers done; also fences Q stores (iter 0)
        #pragma unroll
        for (int it = 0; it < 4; it++) {
            int lin = tid + it * 256;
            int row = lin >> 4;
            int c   = (lin & 15) << 2;
            *(float4*)&Ks[row*68 + c] = *(const float4*)&Kg[(size_t)(kt*64 + row) * DK + c];
            *(float4*)&Vs[row*64 + c] = *(const float4*)&Vg[(size_t)(kt*64 + row) * DK + c];
        }
        __syncthreads();

        // S = Q K^T (4x4 per thread), vectorized over d
        float s[4][4];
        #pragma unroll
        for (int i = 0; i < 4; i++)
            #pragma unroll
            for (int j = 0; j < 4; j++) s[i][j] = 0.f;

        #pragma unroll
        for (int d4 = 0; d4 < 16; d4++) {
            float4 qv[4], kv[4];
            #pragma unroll
            for (int i = 0; i < 4; i++) qv[i] = *(const float4*)&Qs[(r0+i)*64 + d4*4];
            #pragma unroll
            for (int j = 0; j < 4; j++) kv[j] = *(const float4*)&Ks[(c0+j)*68 + d4*4];
            #pragma unroll
            for (int i = 0; i < 4; i++)
                #pragma unroll
                for (int j = 0; j < 4; j++)
                    s[i][j] += qv[i].x*kv[j].x + qv[i].y*kv[j].y
                             + qv[i].z*kv[j].z + qv[i].w*kv[j].w;
        }

        const bool diag = (kt == qt);
        #pragma unroll
        for (int i = 0; i < 4; i++) {
            int qpos = r0 + i;   // in-tile positions comparable on the diagonal tile
            float rmax = -1e30f;
            #pragma unroll
            for (int j = 0; j < 4; j++) {
                if (diag && (c0 + j > qpos)) s[i][j] = -1e30f;
                rmax = fmaxf(rmax, s[i][j]);
            }
            #pragma unroll
            for (int off = 8; off; off >>= 1)
                rmax = fmaxf(rmax, __shfl_xor_sync(0xffffffffu, rmax, off));
            float nm   = fmaxf(m_i[i], rmax);
            float corr = __expf(m_i[i] - nm);
            float rsum = 0.f;
            #pragma unroll
            for (int j = 0; j < 4; j++) {
                float p = __expf(s[i][j] - nm);
                s[i][j] = p;
                rsum += p;
            }
            #pragma unroll
            for (int off = 8; off; off >>= 1)
                rsum += __shfl_xor_sync(0xffffffffu, rsum, off);
            l_i[i] = l_i[i] * corr + rsum;
            m_i[i] = nm;
            #pragma unroll
            for (int j = 0; j < 4; j++) acc[i][j] *= corr;
        }

        // stage P
        #pragma unroll
        for (int i = 0; i < 4; i++)
            *(float4*)&Ps[(r0+i)*64 + c0] = make_float4(s[i][0], s[i][1], s[i][2], s[i][3]);
        __syncthreads();

        // O += P V
        #pragma unroll
        for (int j4 = 0; j4 < 16; j4++) {
            float4 pv[4], vv[4];
            #pragma unroll
            for (int i = 0; i < 4; i++)  pv[i] = *(const float4*)&Ps[(r0+i)*64 + j4*4];
            #pragma unroll
            for (int jj = 0; jj < 4; jj++) vv[jj] = *(const float4*)&Vs[(j4*4 + jj)*64 + c0];
            #pragma unroll
            for (int i = 0; i < 4; i++) {
                acc[i][0] += pv[i].x*vv[0].x + pv[i].y*vv[1].x + pv[i].z*vv[2].x + pv[i].w*vv[3].x;
                acc[i][1] += pv[i].x*vv[0].y + pv[i].y*vv[1].y + pv[i].z*vv[2].y + pv[i].w*vv[3].y;
                acc[i][2] += pv[i].x*vv[0].z + pv[i].y*vv[1].z + pv[i].z*vv[2].z + pv[i].w*vv[3].z;
                acc[i][3] += pv[i].x*vv[0].w + pv[i].y*vv[1].w + pv[i].z*vv[2].w + pv[i].w*vv[3].w;
            }
        }
    }

    // epilogue: ctx[b, t, h*64 + d] = acc / l
    #pragma unroll
    for (int i = 0; i < 4; i++) {
        int qpos = qt*64 + r0 + i;
        float inv = 1.f / l_i[i];
        float4 o;
        o.x = acc[i][0]*inv; o.y = acc[i][1]*inv;
        o.z = acc[i][2]*inv; o.w = acc[i][3]*inv;
        *(float4*)&g_ctx[(size_t)(b*TT + qpos)*DMODEL + h*DK + c0] = o;
    }
}

// ---------------------------------------------------------------------------

extern "C" void kernel_launch(void* const* d_in, const int* in_sizes, int n_in,
                              void* d_out, int out_size)
{
    const float* q  = (const float*)d_in[0];
    // d_in[1] = mask (causal by construction; enforced analytically in attn_kernel)
    const float* Wq = (const float*)d_in[2];
    const float* bq = (const float*)d_in[3];
    const float* Wk = (const float*)d_in[4];
    const float* bk = (const float*)d_in[5];
    const float* Wv = (const float*)d_in[6];
    const float* bv = (const float*)d_in[7];
    const float* Wo = (const float*)d_in[8];
    const float* bo = (const float*)d_in[9];
    float* out = (float*)d_out;

    dim3 blk(256);

    // 1) fused QKV projection: (8192 x 1024) @ (3072 x 1024)^T
    gemm_kernel<0><<<dim3(24, 64), blk>>>(q, Wq, Wk, Wv, bq, bk, bv, nullptr);

    // 2) causal flash attention
    size_t smem = (size_t)(64*64 + 64*68 + 64*64 + 64*64) * sizeof(float);  // 66560 B
    cudaFuncSetAttribute(attn_kernel, cudaFuncAttributeMaxDynamicSharedMemorySize, (int)smem);
    attn_kernel<<<dim3(32, NH, BB), blk, smem>>>();

    // 3) output projection: (8192 x 1024) @ (1024 x 1024)^T
    gemm_kernel<1><<<dim3(8, 64), blk>>>(nullptr, Wo, nullptr, nullptr, bo, nullptr, nullptr, out);
}

// round 2
// speedup vs baseline: 3.6861x; 3.6861x over previous
#include <cuda_runtime.h>
#include <math.h>
#include <stdint.h>

#define DMODEL 1024
#define NH 16
#define DK 64
#define BB 4
#define TT 2048
#define MTOT (BB*TT)   // 8192

// Scratch (alloc-free rule: __device__ globals)
__device__ float g_q[BB*NH*TT*DK];     // (b,h,t,d)
__device__ float g_k[BB*NH*TT*DK];
__device__ float g_v[BB*NH*TT*DK];
__device__ float g_ctx[MTOT*DMODEL];   // (b,t,h*dk)

__device__ __forceinline__ unsigned tf32r(float f) {
    unsigned r;
    asm("cvt.rna.tf32.f32 %0, %1;" : "=r"(r) : "f"(f));
    return r;
}

__device__ __forceinline__ void mma8(float c[4], const unsigned a[4], const unsigned b[2]) {
    asm volatile(
        "mma.sync.aligned.m16n8k8.row.col.f32.tf32.tf32.f32 "
        "{%0,%1,%2,%3}, {%4,%5,%6,%7}, {%8,%9}, {%0,%1,%2,%3};"
        : "+f"(c[0]), "+f"(c[1]), "+f"(c[2]), "+f"(c[3])
        : "r"(a[0]), "r"(a[1]), "r"(a[2]), "r"(a[3]), "r"(b[0]), "r"(b[1]));
}

// ---------------------------------------------------------------------------
// tf32 GEMM: Y[m,n] = sum_k A[m,k] * W[n,k] + bias[n]
// 128x128x32 tile, 256 threads (8 warps, 4x2), warp tile 32x64.
// Smem layout [row][k], stride 36 floats -> fragment LDS bank = 4*gid+tig
// (a 0..31 permutation, conflict-free); STS.128 conflict-free too.
// MODE 0: fused QKV (N=3072 over Wq|Wk|Wv) -> scatter head-major to g_q/g_k/g_v
// MODE 1: output projection (A = g_ctx) -> row-major d_out
// ---------------------------------------------------------------------------
template<int MODE>
__global__ void __launch_bounds__(256, 2)
gemm_tf32(const float* __restrict__ A,
          const float* __restrict__ W0, const float* __restrict__ W1, const float* __restrict__ W2,
          const float* __restrict__ b0v, const float* __restrict__ b1v, const float* __restrict__ b2v,
          float* __restrict__ out)
{
    __shared__ unsigned As[128*36];
    __shared__ unsigned Bs[128*36];

    const int m0  = blockIdx.y * 128;
    const int n0g = blockIdx.x * 128;

    int which = 0, nn0 = n0g;
    const float* W    = W0;
    const float* bias = b0v;
    if (MODE == 0) {
        which = n0g >> 10;            // 128-tile never straddles a 1024 boundary
        nn0   = n0g & 1023;
        W     = (which == 0) ? W0  : (which == 1 ? W1  : W2);
        bias  = (which == 0) ? b0v : (which == 1 ? b1v : b2v);
    }
    const float* Ap = (MODE == 0) ? A : g_ctx;

    const int tid  = threadIdx.x;
    const int warp = tid >> 5;
    const int lane = tid & 31;
    const int gid  = lane >> 2;   // 0..7
    const int tig  = lane & 3;    // 0..3
    const int wm   = warp & 3;    // 4 warps along M
    const int wn   = warp >> 2;   // 2 warps along N
    const int am   = wm * 32;
    const int bn   = wn * 64;

    float acc[2][8][4];
    #pragma unroll
    for (int mt = 0; mt < 2; mt++)
        #pragma unroll
        for (int nt = 0; nt < 8; nt++)
            #pragma unroll
            for (int c = 0; c < 4; c++) acc[mt][nt][c] = 0.f;

    for (int k0 = 0; k0 < DMODEL; k0 += 32) {
        __syncthreads();
        #pragma unroll
        for (int it = 0; it < 4; it++) {
            int lin = tid + it * 256;
            int row = lin >> 3;
            int k4  = (lin & 7) << 2;
            float4 av = *(const float4*)&Ap[(size_t)(m0 + row) * DMODEL + k0 + k4];
            uint4 at; at.x = tf32r(av.x); at.y = tf32r(av.y); at.z = tf32r(av.z); at.w = tf32r(av.w);
            *(uint4*)&As[row*36 + k4] = at;
            float4 wv = *(const float4*)&W[(size_t)(nn0 + row) * DMODEL + k0 + k4];
            uint4 wt; wt.x = tf32r(wv.x); wt.y = tf32r(wv.y); wt.z = tf32r(wv.z); wt.w = tf32r(wv.w);
            *(uint4*)&Bs[row*36 + k4] = wt;
        }
        __syncthreads();

        #pragma unroll
        for (int ks = 0; ks < 4; ks++) {
            const int kk = ks * 8;
            unsigned a[2][4];
            #pragma unroll
            for (int mt = 0; mt < 2; mt++) {
                int r = am + mt*16 + gid;
                a[mt][0] = As[r*36       + kk + tig];
                a[mt][1] = As[(r+8)*36   + kk + tig];
                a[mt][2] = As[r*36       + kk + tig + 4];
                a[mt][3] = As[(r+8)*36   + kk + tig + 4];
            }
            unsigned bf[8][2];
            #pragma unroll
            for (int nt = 0; nt < 8; nt++) {
                int nr = bn + nt*8 + gid;
                bf[nt][0] = Bs[nr*36 + kk + tig];
                bf[nt][1] = Bs[nr*36 + kk + tig + 4];
            }
            #pragma unroll
            for (int mt = 0; mt < 2; mt++)
                #pragma unroll
                for (int nt = 0; nt < 8; nt++)
                    mma8(acc[mt][nt], a[mt], bf[nt]);
        }
    }

    // epilogue: C frag (row = gid/gid+8, cols = 2*tig, 2*tig+1)
    #pragma unroll
    for (int mt = 0; mt < 2; mt++) {
        int mrow = m0 + am + mt*16 + gid;
        #pragma unroll
        for (int nt = 0; nt < 8; nt++) {
            int nn = nn0 + ((MODE == 0) ? 0 : 0) + bn + nt*8 + 2*tig;
            float2 bia = *(const float2*)&bias[nn];
            float2 v0, v1;
            v0.x = acc[mt][nt][0] + bia.x;  v0.y = acc[mt][nt][1] + bia.y;
            v1.x = acc[mt][nt][2] + bia.x;  v1.y = acc[mt][nt][3] + bia.y;
            if (MODE == 0) {
                float* dst = (which == 0) ? g_q : (which == 1 ? g_k : g_v);
                int hh = nn >> 6, dd = nn & 63;
                int bidx = mrow >> 11, t = mrow & 2047;
                size_t o0 = ((size_t)((bidx*NH + hh)*TT + t)) * DK + dd;
                size_t o1 = ((size_t)((bidx*NH + hh)*TT + t + 8)) * DK + dd;
                *(float2*)&dst[o0] = v0;
                *(float2*)&dst[o1] = v1;
            } else {
                *(float2*)&out[(size_t)mrow * DMODEL + nn]       = v0;
                *(float2*)&out[(size_t)(mrow+8) * DMODEL + nn]   = v1;
            }
        }
    }
}

// ---------------------------------------------------------------------------
// Causal flash attention on tensor cores. One block = (qt, h, b), 128 threads
// (4 warps). Warp w owns q rows [16w,16w+16): S tile 16x64 in mma C-fragments,
// register online softmax (quad shuffles), P staged in per-warp-private smem
// (tf32) as A operand for PV. K/V tiles in smem stride-68 (conflict-free).
// ---------------------------------------------------------------------------
__global__ void __launch_bounds__(128, 3)
attn_tf32()
{
    extern __shared__ unsigned sm[];
    unsigned* Ks = sm;                // 64*68
    unsigned* Vs = Ks + 64*68;        // 64*68
    unsigned* Ps = Vs + 64*68;        // 64*68 (per-warp private 16-row bands)

    const int qt  = 31 - (int)blockIdx.x;   // big causal tiles first
    const int h   = blockIdx.y;
    const int b   = blockIdx.z;
    const int tid  = threadIdx.x;
    const int warp = tid >> 5;
    const int lane = tid & 31;
    const int gid  = lane >> 2;
    const int tig  = lane & 3;

    const size_t base = (size_t)(b*NH + h) * TT * DK;
    const float* Qg = g_q + base;
    const float* Kg = g_k + base;
    const float* Vg = g_v + base;

    // preload Q fragments (scaled by 1/8, tf32): 8 k-steps x 4 regs
    unsigned qf[8][4];
    {
        const int r0 = qt*64 + warp*16 + gid;
        #pragma unroll
        for (int ks = 0; ks < 8; ks++) {
            qf[ks][0] = tf32r(Qg[(size_t)r0*DK     + ks*8 + tig]     * 0.125f);
            qf[ks][1] = tf32r(Qg[(size_t)(r0+8)*DK + ks*8 + tig]     * 0.125f);
            qf[ks][2] = tf32r(Qg[(size_t)r0*DK     + ks*8 + tig + 4] * 0.125f);
            qf[ks][3] = tf32r(Qg[(size_t)(r0+8)*DK + ks*8 + tig + 4] * 0.125f);
        }
    }

    float o[8][4];
    #pragma unroll
    for (int nt = 0; nt < 8; nt++)
        #pragma unroll
        for (int c = 0; c < 4; c++) o[nt][c] = 0.f;
    float m0r = -1e30f, m1r = -1e30f, l0 = 0.f, l1 = 0.f;

    const int prow0 = warp*16 + gid;        // P smem rows for this thread
    const int prow1 = prow0 + 8;

    for (int kt = 0; kt <= qt; kt++) {
        __syncthreads();
        #pragma unroll
        for (int it = 0; it < 8; it++) {
            int lin = tid + it * 128;
            int row = lin >> 4;
            int c4  = (lin & 15) << 2;
            float4 kv = *(const float4*)&Kg[(size_t)(kt*64 + row)*DK + c4];
            uint4 ku; ku.x = tf32r(kv.x); ku.y = tf32r(kv.y); ku.z = tf32r(kv.z); ku.w = tf32r(kv.w);
            *(uint4*)&Ks[row*68 + c4] = ku;
            float4 vv = *(const float4*)&Vg[(size_t)(kt*64 + row)*DK + c4];
            uint4 vu; vu.x = tf32r(vv.x); vu.y = tf32r(vv.y); vu.z = tf32r(vv.z); vu.w = tf32r(vv.w);
            *(uint4*)&Vs[row*68 + c4] = vu;
        }
        __syncthreads();

        // S = Q K^T : 16x64 per warp
        float s[8][4];
        #pragma unroll
        for (int nt = 0; nt < 8; nt++)
            #pragma unroll
            for (int c = 0; c < 4; c++) s[nt][c] = 0.f;

        #pragma unroll
        for (int ks = 0; ks < 8; ks++) {
            unsigned bf[2];
            #pragma unroll
            for (int nt = 0; nt < 8; nt++) {
                int tr = nt*8 + gid;
                bf[0] = Ks[tr*68 + ks*8 + tig];
                bf[1] = Ks[tr*68 + ks*8 + tig + 4];
                mma8(s[nt], qf[ks], bf);
            }
        }

        // causal mask on the diagonal tile
        if (kt == qt) {
            const int r0l = warp*16 + gid;
            #pragma unroll
            for (int nt = 0; nt < 8; nt++) {
                int col = nt*8 + 2*tig;
                if (col     > r0l)     s[nt][0] = -1e30f;
                if (col + 1 > r0l)     s[nt][1] = -1e30f;
                if (col     > r0l + 8) s[nt][2] = -1e30f;
                if (col + 1 > r0l + 8) s[nt][3] = -1e30f;
            }
        }

        // online softmax (rows r0: c0/c1, r1: c2/c3); quad = lanes sharing gid
        float mx0 = -1e30f, mx1 = -1e30f;
        #pragma unroll
        for (int nt = 0; nt < 8; nt++) {
            mx0 = fmaxf(mx0, fmaxf(s[nt][0], s[nt][1]));
            mx1 = fmaxf(mx1, fmaxf(s[nt][2], s[nt][3]));
        }
        mx0 = fmaxf(mx0, __shfl_xor_sync(0xffffffffu, mx0, 1));
        mx0 = fmaxf(mx0, __shfl_xor_sync(0xffffffffu, mx0, 2));
        mx1 = fmaxf(mx1, __shfl_xor_sync(0xffffffffu, mx1, 1));
        mx1 = fmaxf(mx1, __shfl_xor_sync(0xffffffffu, mx1, 2));

        float nm0 = fmaxf(m0r, mx0), nm1 = fmaxf(m1r, mx1);
        float corr0 = __expf(m0r - nm0), corr1 = __expf(m1r - nm1);
        float rs0 = 0.f, rs1 = 0.f;
        #pragma unroll
        for (int nt = 0; nt < 8; nt++) {
            s[nt][0] = __expf(s[nt][0] - nm0);
            s[nt][1] = __expf(s[nt][1] - nm0);
            s[nt][2] = __expf(s[nt][2] - nm1);
            s[nt][3] = __expf(s[nt][3] - nm1);
            rs0 += s[nt][0] + s[nt][1];
            rs1 += s[nt][2] + s[nt][3];
        }
        rs0 += __shfl_xor_sync(0xffffffffu, rs0, 1);
        rs0 += __shfl_xor_sync(0xffffffffu, rs0, 2);
        rs1 += __shfl_xor_sync(0xffffffffu, rs1, 1);
        rs1 += __shfl_xor_sync(0xffffffffu, rs1, 2);
        l0 = l0 * corr0 + rs0;  m0r = nm0;
        l1 = l1 * corr1 + rs1;  m1r = nm1;
        #pragma unroll
        for (int nt = 0; nt < 8; nt++) {
            o[nt][0] *= corr0;  o[nt][1] *= corr0;
            o[nt][2] *= corr1;  o[nt][3] *= corr1;
        }

        // stage P (tf32) into this warp's private band
        __syncwarp();
        #pragma unroll
        for (int nt = 0; nt < 8; nt++) {
            uint2 p0; p0.x = tf32r(s[nt][0]); p0.y = tf32r(s[nt][1]);
            uint2 p1; p1.x = tf32r(s[nt][2]); p1.y = tf32r(s[nt][3]);
            *(uint2*)&Ps[prow0*68 + nt*8 + 2*tig] = p0;
            *(uint2*)&Ps[prow1*68 + nt*8 + 2*tig] = p1;
        }
        __syncwarp();

        // O += P V : A = P (m16 k64), B = V (k64 n64)
        #pragma unroll
        for (int ks = 0; ks < 8; ks++) {
            unsigned pa[4];
            pa[0] = Ps[prow0*68 + ks*8 + tig];
            pa[1] = Ps[prow1*68 + ks*8 + tig];
            pa[2] = Ps[prow0*68 + ks*8 + tig + 4];
            pa[3] = Ps[prow1*68 + ks*8 + tig + 4];
            unsigned vb[2];
            #pragma unroll
            for (int nt = 0; nt < 8; nt++) {
                vb[0] = Vs[(ks*8 + tig)*68     + nt*8 + gid];
                vb[1] = Vs[(ks*8 + tig + 4)*68 + nt*8 + gid];
                mma8(o[nt], pa, vb);
            }
        }
    }

    // epilogue: ctx[b, t, h*64 + d] = O / l
    const float inv0 = 1.f / l0, inv1 = 1.f / l1;
    const int grow0 = b*TT + qt*64 + warp*16 + gid;
    #pragma unroll
    for (int nt = 0; nt < 8; nt++) {
        int dd = h*DK + nt*8 + 2*tig;
        float2 w0; w0.x = o[nt][0]*inv0; w0.y = o[nt][1]*inv0;
        float2 w1; w1.x = o[nt][2]*inv1; w1.y = o[nt][3]*inv1;
        *(float2*)&g_ctx[(size_t)grow0*DMODEL + dd]       = w0;
        *(float2*)&g_ctx[(size_t)(grow0+8)*DMODEL + dd]   = w1;
    }
}

// ---------------------------------------------------------------------------

extern "C" void kernel_launch(void* const* d_in, const int* in_sizes, int n_in,
                              void* d_out, int out_size)
{
    const float* q  = (const float*)d_in[0];
    // d_in[1] = mask (causal by construction; applied analytically)
    const float* Wq = (const float*)d_in[2];
    const float* bq = (const float*)d_in[3];
    const float* Wk = (const float*)d_in[4];
    const float* bk = (const float*)d_in[5];
    const float* Wv = (const float*)d_in[6];
    const float* bv = (const float*)d_in[7];
    const float* Wo = (const float*)d_in[8];
    const float* bo = (const float*)d_in[9];
    float* out = (float*)d_out;

    // 1) fused QKV projection (tf32 tensor cores)
    gemm_tf32<0><<<dim3(24, 64), 256>>>(q, Wq, Wk, Wv, bq, bk, bv, nullptr);

    // 2) causal flash attention (tf32 tensor cores)
    size_t smem = (size_t)(3 * 64 * 68) * sizeof(unsigned);   // 52224 B
    static int attn_attr_set = 0;
    cudaFuncSetAttribute(attn_tf32, cudaFuncAttributeMaxDynamicSharedMemorySize, (int)smem);
    (void)attn_attr_set;
    attn_tf32<<<dim3(32, NH, BB), 128, smem>>>();

    // 3) output projection
    gemm_tf32<1><<<dim3(8, 64), 256>>>(nullptr, Wo, nullptr, nullptr, bo, nullptr, nullptr, out);
}

// round 6
// speedup vs baseline: 4.2860x; 1.1628x over previous
#include <cuda_runtime.h>
#include <math.h>
#include <stdint.h>

#define DMODEL 1024
#define NH 16
#define DK 64
#define BB 4
#define TT 2048
#define MTOT (BB*TT)   // 8192

// Scratch (alloc-free rule: __device__ globals)
__device__ float g_q[BB*NH*TT*DK];       // (b,h,t,d)   tf32-exact
__device__ float g_k[BB*NH*TT*DK];       // tf32-exact
__device__ float g_v[BB*NH*TT*DK];       // tf32-exact
__device__ float g_ctx[MTOT*DMODEL];     // (b,t,h*dk)  tf32-exact
__device__ float g_qr[MTOT*DMODEL];      // q pre-rounded to tf32
__device__ float g_wr[4*DMODEL*DMODEL];  // Wq|Wk|Wv|Wo pre-rounded to tf32

// ---------------------------------------------------------------------------
// helpers
// ---------------------------------------------------------------------------
__device__ __forceinline__ unsigned tf32r(float f) {
    unsigned r;
    asm("cvt.rna.tf32.f32 %0, %1;" : "=r"(r) : "f"(f));
    return r;
}
__device__ __forceinline__ float tf32rf(float f) { return __uint_as_float(tf32r(f)); }

__device__ __forceinline__ uint32_t smem_u32(const void* p) {
    uint32_t a;
    asm("{ .reg .u64 t; cvta.to.shared.u64 t, %1; cvt.u32.u64 %0, t; }" : "=r"(a) : "l"(p));
    return a;
}
__device__ __forceinline__ void cpasync16(uint32_t saddr, const void* g) {
    asm volatile("cp.async.cg.shared.global [%0], [%1], 16;" :: "r"(saddr), "l"(g));
}
#define CP_COMMIT()  asm volatile("cp.async.commit_group;" ::: "memory")
#define CP_WAIT(n)   asm volatile("cp.async.wait_group %0;" :: "n"(n) : "memory")

__device__ __forceinline__ void mma8(float c[4], const unsigned a[4], const unsigned b[2]) {
    asm volatile(
        "mma.sync.aligned.m16n8k8.row.col.f32.tf32.tf32.f32 "
        "{%0,%1,%2,%3}, {%4,%5,%6,%7}, {%8,%9}, {%0,%1,%2,%3};"
        : "+f"(c[0]), "+f"(c[1]), "+f"(c[2]), "+f"(c[3])
        : "r"(a[0]), "r"(a[1]), "r"(a[2]), "r"(a[3]), "r"(b[0]), "r"(b[1]));
}

// ---------------------------------------------------------------------------
// pre-round passes (rna -> tf32-exact fp32)
// ---------------------------------------------------------------------------
__global__ void __launch_bounds__(256)
round_w_kernel(const float* __restrict__ wq, const float* __restrict__ wk,
               const float* __restrict__ wv, const float* __restrict__ wo)
{
    const int i = blockIdx.x * 256 + threadIdx.x;
    const float4* src[4] = { (const float4*)wq, (const float4*)wk,
                             (const float4*)wv, (const float4*)wo };
    float4* dst = (float4*)g_wr;
    #pragma unroll
    for (int m = 0; m < 4; m++) {
        float4 v = src[m][i];
        v.x = tf32rf(v.x); v.y = tf32rf(v.y); v.z = tf32rf(v.z); v.w = tf32rf(v.w);
        dst[(size_t)m * (DMODEL*DMODEL/4) + i] = v;
    }
}
__global__ void __launch_bounds__(256)
round_q_kernel(const float* __restrict__ q)
{
    const int i = blockIdx.x * 256 + threadIdx.x;
    float4 v = ((const float4*)q)[i];
    v.x = tf32rf(v.x); v.y = tf32rf(v.y); v.z = tf32rf(v.z); v.w = tf32rf(v.w);
    ((float4*)g_qr)[i] = v;
}

// ---------------------------------------------------------------------------
// tf32 mma.sync GEMM: Y[m,n] = sum_k A[m,k]*W[n,k] + bias[n]
// Block 128x128, 128 threads (4 warps, 2x2), warp tile 64x64 (1.0 LDS/mma).
// KC=32, 3-stage cp.async pipeline. Smem rows stride 36 floats: fragment LDS
// bank = (4*gid + tig) & 31 -> exact permutation, conflict-free.
// MODE 0: A=g_qr, W in {Wq,Wk,Wv} per n-tile -> head-major g_q/g_k/g_v (tf32-rounded)
// MODE 1: A=g_ctx, W=Wo -> row-major d_out (full fp32)
// ---------------------------------------------------------------------------
#define GKC    32
#define GNCH   (DMODEL/GKC)       // 32
#define GROWB  144                // 36 floats
#define GTILEB (128*GROWB)        // 18432
#define GSTAGE (2*GTILEB)         // A + B = 36864
#define GSMEM  (3*GSTAGE)         // 110592

template<int MODE>
__global__ void __launch_bounds__(128, 2)
gemm_mma(const float* __restrict__ bq, const float* __restrict__ bk,
         const float* __restrict__ bv, const float* __restrict__ bo,
         float* __restrict__ out)
{
    extern __shared__ char smem[];
    const uint32_t sb = smem_u32(smem);

    const int tid  = threadIdx.x;
    const int wid  = tid >> 5;
    const int lane = tid & 31;
    const int gid  = lane >> 2;
    const int tig  = lane & 3;
    const int am   = (wid & 1) * 64;
    const int bn   = (wid >> 1) * 64;

    const int m0  = blockIdx.y * 128;
    const int n0g = blockIdx.x * 128;

    int which = 3, nn0 = n0g;
    const float* bias = bo;
    if (MODE == 0) {
        which = n0g >> 10;                // 128-tile never straddles 1024
        nn0   = n0g & 1023;
        bias  = (which == 0) ? bq : (which == 1 ? bk : bv);
    }
    const float* A = (MODE == 0) ? g_qr : g_ctx;
    const float* W = g_wr + (size_t)which * DMODEL * DMODEL;

    float acc[4][8][4];
    #pragma unroll
    for (int mt = 0; mt < 4; mt++)
        #pragma unroll
        for (int nt = 0; nt < 8; nt++)
            #pragma unroll
            for (int c = 0; c < 4; c++) acc[mt][nt][c] = 0.f;

    auto load_chunk = [&](int c, int st) {
        const uint32_t sa = sb + st * GSTAGE;
        #pragma unroll
        for (int it = 0; it < 8; it++) {
            int lin = tid + it * 128;
            int row = lin >> 3, ch = lin & 7;
            cpasync16(sa + row*GROWB + ch*16,
                      A + (size_t)(m0 + row) * DMODEL + c*GKC + ch*4);
        }
        const uint32_t sB = sa + GTILEB;
        #pragma unroll
        for (int it = 0; it < 8; it++) {
            int lin = tid + it * 128;
            int row = lin >> 3, ch = lin & 7;
            cpasync16(sB + row*GROWB + ch*16,
                      W + (size_t)(nn0 + row) * DMODEL + c*GKC + ch*4);
        }
        CP_COMMIT();
    };

    load_chunk(0, 0);
    load_chunk(1, 1);

    for (int i = 0; i < GNCH; i++) {
        __syncthreads();                      // stage (i+2)%3 free for overwrite
        if (i + 2 < GNCH) load_chunk(i + 2, (i + 2) % 3);
        if (i + 2 < GNCH)      { CP_WAIT(2); }
        else if (i + 1 < GNCH) { CP_WAIT(1); }
        else                   { CP_WAIT(0); }
        __syncthreads();                      // stage i visible to all warps

        const unsigned* Au = (const unsigned*)(smem + (i % 3) * GSTAGE);
        const unsigned* Bu = (const unsigned*)(smem + (i % 3) * GSTAGE + GTILEB);
        #pragma unroll
        for (int ks = 0; ks < 4; ks++) {
            const int kk = ks * 8;
            unsigned a[4][4];
            #pragma unroll
            for (int mt = 0; mt < 4; mt++) {
                int r = am + mt*16 + gid;
                a[mt][0] = Au[r*36       + kk + tig];
                a[mt][1] = Au[(r+8)*36   + kk + tig];
                a[mt][2] = Au[r*36       + kk + tig + 4];
                a[mt][3] = Au[(r+8)*36   + kk + tig + 4];
            }
            unsigned bf[8][2];
            #pragma unroll
            for (int nt = 0; nt < 8; nt++) {
                int nr = bn + nt*8 + gid;
                bf[nt][0] = Bu[nr*36 + kk + tig];
                bf[nt][1] = Bu[nr*36 + kk + tig + 4];
            }
            #pragma unroll
            for (int mt = 0; mt < 4; mt++)
                #pragma unroll
                for (int nt = 0; nt < 8; nt++)
                    mma8(acc[mt][nt], a[mt], bf[nt]);
        }
    }

    // epilogue
    #pragma unroll
    for (int mt = 0; mt < 4; mt++) {
        int mrow = m0 + am + mt*16 + gid;
        #pragma unroll
        for (int nt = 0; nt < 8; nt++) {
            int nn = nn0 + bn + nt*8 + 2*tig;
            float2 bia = *(const float2*)&bias[nn];
            if (MODE == 0) {
                float2 v0, v1;
                v0.x = tf32rf(acc[mt][nt][0] + bia.x);  v0.y = tf32rf(acc[mt][nt][1] + bia.y);
                v1.x = tf32rf(acc[mt][nt][2] + bia.x);  v1.y = tf32rf(acc[mt][nt][3] + bia.y);
                float* dst = (which == 0) ? g_q : (which == 1 ? g_k : g_v);
                int hh = nn >> 6, dd = nn & 63;
                int bidx = mrow >> 11, t = mrow & 2047;
                *(float2*)&dst[((size_t)((bidx*NH + hh)*TT + t)) * DK + dd]     = v0;
                *(float2*)&dst[((size_t)((bidx*NH + hh)*TT + t + 8)) * DK + dd] = v1;
            } else {
                float2 v0, v1;
                v0.x = acc[mt][nt][0] + bia.x;  v0.y = acc[mt][nt][1] + bia.y;
                v1.x = acc[mt][nt][2] + bia.x;  v1.y = acc[mt][nt][3] + bia.y;
                *(float2*)&out[(size_t)mrow * DMODEL + nn]     = v0;
                *(float2*)&out[(size_t)(mrow+8) * DMODEL + nn] = v1;
            }
        }
    }
}

// ---------------------------------------------------------------------------
// Causal flash attention, tf32 mma.sync, cp.async double-buffered K/V.
// One block = (qt, h, b), 128 threads (4 warps), warp owns 16 q rows.
// K smem stride 68 floats (bank perm 4*gid+tig), V stride 72 (perm 8*tig+gid).
// g_q/g_k/g_v are tf32-exact -> raw bits feed mma directly.
// ---------------------------------------------------------------------------
#define AKB   (64*68*4)           // 17408
#define AVB   (64*72*4)           // 18432
#define ASTG  (AKB+AVB)           // 35840
#define APOFF (2*ASTG)            // Ps at 71680
#define ASMEM (APOFF + 64*68*4)   // 89088

__global__ void __launch_bounds__(128, 2)
attn_tf32()
{
    extern __shared__ char smem[];
    const uint32_t sb = smem_u32(smem);

    const int qt  = 31 - (int)blockIdx.x;   // big causal tiles first
    const int h   = blockIdx.y;
    const int b   = blockIdx.z;
    const int tid  = threadIdx.x;
    const int warp = tid >> 5;
    const int lane = tid & 31;
    const int gid  = lane >> 2;
    const int tig  = lane & 3;

    const size_t base = (size_t)(b*NH + h) * TT * DK;
    const float* Qg = g_q + base;
    const float* Kg = g_k + base;
    const float* Vg = g_v + base;

    unsigned* Ps = (unsigned*)(smem + APOFF);

    // Q fragments (scaled by 1/8 — exact on tf32-exact values)
    unsigned qf[8][4];
    {
        const int r0 = qt*64 + warp*16 + gid;
        #pragma unroll
        for (int ks = 0; ks < 8; ks++) {
            qf[ks][0] = tf32r(Qg[(size_t)r0*DK     + ks*8 + tig]     * 0.125f);
            qf[ks][1] = tf32r(Qg[(size_t)(r0+8)*DK + ks*8 + tig]     * 0.125f);
            qf[ks][2] = tf32r(Qg[(size_t)r0*DK     + ks*8 + tig + 4] * 0.125f);
            qf[ks][3] = tf32r(Qg[(size_t)(r0+8)*DK + ks*8 + tig + 4] * 0.125f);
        }
    }

    float o[8][4];
    #pragma unroll
    for (int nt = 0; nt < 8; nt++)
        #pragma unroll
        for (int c = 0; c < 4; c++) o[nt][c] = 0.f;
    float m0r = -1e30f, m1r = -1e30f, l0 = 0.f, l1 = 0.f;

    const int prow0 = warp*16 + gid;
    const int prow1 = prow0 + 8;

    auto load_kv = [&](int kt, int st) {
        const uint32_t sK = sb + st * ASTG;
        const uint32_t sV = sK + AKB;
        #pragma unroll
        for (int it = 0; it < 8; it++) {
            int lin = tid + it * 128;
            int row = lin >> 4, ch = lin & 15;
            cpasync16(sK + row*272 + ch*16, Kg + (size_t)(kt*64 + row)*DK + ch*4);
            cpasync16(sV + row*288 + ch*16, Vg + (size_t)(kt*64 + row)*DK + ch*4);
        }
        CP_COMMIT();
    };

    load_kv(0, 0);

    for (int kt = 0; kt <= qt; kt++) {
        __syncthreads();                         // other stage free
        if (kt < qt) { load_kv(kt + 1, (kt + 1) & 1); CP_WAIT(1); }
        else         { CP_WAIT(0); }
        __syncthreads();                         // stage kt visible

        const unsigned* Ks = (const unsigned*)(smem + (kt & 1) * ASTG);
        const unsigned* Vs = (const unsigned*)(smem + (kt & 1) * ASTG + AKB);

        // S = Q K^T : 16x64 per warp
        float s[8][4];
        #pragma unroll
        for (int nt = 0; nt < 8; nt++)
            #pragma unroll
            for (int c = 0; c < 4; c++) s[nt][c] = 0.f;

        #pragma unroll
        for (int ks = 0; ks < 8; ks++) {
            unsigned bf[2];
            #pragma unroll
            for (int nt = 0; nt < 8; nt++) {
                int tr = nt*8 + gid;
                bf[0] = Ks[tr*68 + ks*8 + tig];
                bf[1] = Ks[tr*68 + ks*8 + tig + 4];
                mma8(s[nt], qf[ks], bf);
            }
        }

        if (kt == qt) {
            const int r0l = warp*16 + gid;
            #pragma unroll
            for (int nt = 0; nt < 8; nt++) {
                int col = nt*8 + 2*tig;
                if (col     > r0l)     s[nt][0] = -1e30f;
                if (col + 1 > r0l)     s[nt][1] = -1e30f;
                if (col     > r0l + 8) s[nt][2] = -1e30f;
                if (col + 1 > r0l + 8) s[nt][3] = -1e30f;
            }
        }

        // online softmax
        float mx0 = -1e30f, mx1 = -1e30f;
        #pragma unroll
        for (int nt = 0; nt < 8; nt++) {
            mx0 = fmaxf(mx0, fmaxf(s[nt][0], s[nt][1]));
            mx1 = fmaxf(mx1, fmaxf(s[nt][2], s[nt][3]));
        }
        mx0 = fmaxf(mx0, __shfl_xor_sync(0xffffffffu, mx0, 1));
        mx0 = fmaxf(mx0, __shfl_xor_sync(0xffffffffu, mx0, 2));
        mx1 = fmaxf(mx1, __shfl_xor_sync(0xffffffffu, mx1, 1));
        mx1 = fmaxf(mx1, __shfl_xor_sync(0xffffffffu, mx1, 2));

        float nm0 = fmaxf(m0r, mx0), nm1 = fmaxf(m1r, mx1);
        float corr0 = __expf(m0r - nm0), corr1 = __expf(m1r - nm1);
        float rs0 = 0.f, rs1 = 0.f;
        #pragma unroll
        for (int nt = 0; nt < 8; nt++) {
            s[nt][0] = __expf(s[nt][0] - nm0);
            s[nt][1] = __expf(s[nt][1] - nm0);
            s[nt][2] = __expf(s[nt][2] - nm1);
            s[nt][3] = __expf(s[nt][3] - nm1);
            rs0 += s[nt][0] + s[nt][1];
            rs1 += s[nt][2] + s[nt][3];
        }
        rs0 += __shfl_xor_sync(0xffffffffu, rs0, 1);
        rs0 += __shfl_xor_sync(0xffffffffu, rs0, 2);
        rs1 += __shfl_xor_sync(0xffffffffu, rs1, 1);
        rs1 += __shfl_xor_sync(0xffffffffu, rs1, 2);
        l0 = l0 * corr0 + rs0;  m0r = nm0;
        l1 = l1 * corr1 + rs1;  m1r = nm1;
        #pragma unroll
        for (int nt = 0; nt < 8; nt++) {
            o[nt][0] *= corr0;  o[nt][1] *= corr0;
            o[nt][2] *= corr1;  o[nt][3] *= corr1;
        }

        // stage P (tf32) into this warp's private band
        __syncwarp();
        #pragma unroll
        for (int nt = 0; nt < 8; nt++) {
            uint2 p0; p0.x = tf32r(s[nt][0]); p0.y = tf32r(s[nt][1]);
            uint2 p1; p1.x = tf32r(s[nt][2]); p1.y = tf32r(s[nt][3]);
            *(uint2*)&Ps[prow0*68 + nt*8 + 2*tig] = p0;
            *(uint2*)&Ps[prow1*68 + nt*8 + 2*tig] = p1;
        }
        __syncwarp();

        // O += P V
        #pragma unroll
        for (int ks = 0; ks < 8; ks++) {
            unsigned pa[4];
            pa[0] = Ps[prow0*68 + ks*8 + tig];
            pa[1] = Ps[prow1*68 + ks*8 + tig];
            pa[2] = Ps[prow0*68 + ks*8 + tig + 4];
            pa[3] = Ps[prow1*68 + ks*8 + tig + 4];
            unsigned vb[2];
            #pragma unroll
            for (int nt = 0; nt < 8; nt++) {
                vb[0] = Vs[(ks*8 + tig)*72     + nt*8 + gid];
                vb[1] = Vs[(ks*8 + tig + 4)*72 + nt*8 + gid];
                mma8(o[nt], pa, vb);
            }
        }
    }

    // epilogue: ctx (tf32-rounded so the Wo GEMM can consume raw bits)
    const float inv0 = 1.f / l0, inv1 = 1.f / l1;
    const int grow0 = b*TT + qt*64 + warp*16 + gid;
    #pragma unroll
    for (int nt = 0; nt < 8; nt++) {
        int dd = h*DK + nt*8 + 2*tig;
        float2 w0; w0.x = tf32rf(o[nt][0]*inv0); w0.y = tf32rf(o[nt][1]*inv0);
        float2 w1; w1.x = tf32rf(o[nt][2]*inv1); w1.y = tf32rf(o[nt][3]*inv1);
        *(float2*)&g_ctx[(size_t)grow0*DMODEL + dd]     = w0;
        *(float2*)&g_ctx[(size_t)(grow0+8)*DMODEL + dd] = w1;
    }
}

// ---------------------------------------------------------------------------

extern "C" void kernel_launch(void* const* d_in, const int* in_sizes, int n_in,
                              void* d_out, int out_size)
{
    const float* q  = (const float*)d_in[0];
    // d_in[1] = mask (causal by construction; applied analytically)
    const float* Wq = (const float*)d_in[2];
    const float* bq = (const float*)d_in[3];
    const float* Wk = (const float*)d_in[4];
    const float* bk = (const float*)d_in[5];
    const float* Wv = (const float*)d_in[6];
    const float* bv = (const float*)d_in[7];
    const float* Wo = (const float*)d_in[8];
    const float* bo = (const float*)d_in[9];
    float* out = (float*)d_out;

    // 0) pre-round operands to tf32 (rna)
    round_w_kernel<<<1024, 256>>>(Wq, Wk, Wv, Wo);
    round_q_kernel<<<8192, 256>>>(q);

    // 1) fused QKV projection
    cudaFuncSetAttribute(gemm_mma<0>, cudaFuncAttributeMaxDynamicSharedMemorySize, GSMEM);
    gemm_mma<0><<<dim3(24, 64), 128, GSMEM>>>(bq, bk, bv, bo, nullptr);

    // 2) causal flash attention
    cudaFuncSetAttribute(attn_tf32, cudaFuncAttributeMaxDynamicSharedMemorySize, ASMEM);
    attn_tf32<<<dim3(32, NH, BB), 128, ASMEM>>>();

    // 3) output projection
    cudaFuncSetAttribute(gemm_mma<1>, cudaFuncAttributeMaxDynamicSharedMemorySize, GSMEM);
    gemm_mma<1><<<dim3(8, 64), 128, GSMEM>>>(bq, bk, bv, bo, out);
}

// round 9
// speedup vs baseline: 4.3445x; 1.0137x over previous
#include <cuda_runtime.h>
#include <math.h>
#include <stdint.h>

#define DMODEL 1024
#define NH 16
#define DK 64
#define BB 4
#define TT 2048
#define MTOT (BB*TT)   // 8192

// Scratch (alloc-free rule: __device__ globals)
__device__ float g_q[BB*NH*TT*DK];       // (b,h,t,d)   tf32-exact
__device__ float g_k[BB*NH*TT*DK];       // tf32-exact
__device__ float g_v[BB*NH*TT*DK];       // tf32-exact
__device__ float g_ctx[MTOT*DMODEL];     // (b,t,h*dk)  tf32-exact
__device__ float g_qr[MTOT*DMODEL];      // q pre-rounded to tf32
__device__ float g_wr[4*DMODEL*DMODEL];  // Wq|Wk|Wv|Wo pre-rounded to tf32

// ---------------------------------------------------------------------------
// helpers
// ---------------------------------------------------------------------------
__device__ __forceinline__ unsigned tf32r(float f) {
    unsigned r;
    asm("cvt.rna.tf32.f32 %0, %1;" : "=r"(r) : "f"(f));
    return r;
}
__device__ __forceinline__ float tf32rf(float f) { return __uint_as_float(tf32r(f)); }

__device__ __forceinline__ uint32_t smem_u32(const void* p) {
    uint32_t a;
    asm("{ .reg .u64 t; cvta.to.shared.u64 t, %1; cvt.u32.u64 %0, t; }" : "=r"(a) : "l"(p));
    return a;
}
__device__ __forceinline__ void cpasync16(uint32_t saddr, const void* g) {
    asm volatile("cp.async.cg.shared.global [%0], [%1], 16;" :: "r"(saddr), "l"(g));
}
#define CP_COMMIT()  asm volatile("cp.async.commit_group;" ::: "memory")
#define CP_WAIT(n)   asm volatile("cp.async.wait_group %0;" :: "n"(n) : "memory")

__device__ __forceinline__ void mma8(float c[4], const unsigned a[4], const unsigned b[2]) {
    asm volatile(
        "mma.sync.aligned.m16n8k8.row.col.f32.tf32.tf32.f32 "
        "{%0,%1,%2,%3}, {%4,%5,%6,%7}, {%8,%9}, {%0,%1,%2,%3};"
        : "+f"(c[0]), "+f"(c[1]), "+f"(c[2]), "+f"(c[3])
        : "r"(a[0]), "r"(a[1]), "r"(a[2]), "r"(a[3]), "r"(b[0]), "r"(b[1]));
}

// ---------------------------------------------------------------------------
// pre-round passes (rna -> tf32-exact fp32)
// ---------------------------------------------------------------------------
__global__ void __launch_bounds__(256)
round_w_kernel(const float* __restrict__ wq, const float* __restrict__ wk,
               const float* __restrict__ wv, const float* __restrict__ wo)
{
    const int i = blockIdx.x * 256 + threadIdx.x;
    const float4* src[4] = { (const float4*)wq, (const float4*)wk,
                             (const float4*)wv, (const float4*)wo };
    float4* dst = (float4*)g_wr;
    #pragma unroll
    for (int m = 0; m < 4; m++) {
        float4 v = src[m][i];
        v.x = tf32rf(v.x); v.y = tf32rf(v.y); v.z = tf32rf(v.z); v.w = tf32rf(v.w);
        dst[(size_t)m * (DMODEL*DMODEL/4) + i] = v;
    }
}
__global__ void __launch_bounds__(256)
round_q_kernel(const float* __restrict__ q)
{
    const int i = blockIdx.x * 256 + threadIdx.x;
    float4 v = ((const float4*)q)[i];
    v.x = tf32rf(v.x); v.y = tf32rf(v.y); v.z = tf32rf(v.z); v.w = tf32rf(v.w);
    ((float4*)g_qr)[i] = v;
}

// ---------------------------------------------------------------------------
// tf32 mma.sync GEMM: Y[m,n] = sum_k A[m,k]*W[n,k] + bias[n]
// Block 128x128, 128 threads (4 warps, 2x2), warp tile 64x64 (1.0 LDS/mma).
// KC=32, 2-stage cp.async pipeline (72KB smem -> 3 blocks/SM, 12 warps).
// Smem rows stride 36 floats: fragment LDS bank = (4*gid + tig) permutation.
// MODE 0: A=g_qr, W in {Wq,Wk,Wv} per n-tile -> head-major g_q/g_k/g_v (tf32-rounded)
// MODE 1: A=g_ctx, W=Wo -> row-major d_out (full fp32)
// ---------------------------------------------------------------------------
#define GKC    32
#define GNCH   (DMODEL/GKC)       // 32
#define GROWB  144                // 36 floats
#define GTILEB (128*GROWB)        // 18432
#define GSTAGE (2*GTILEB)         // A + B = 36864
#define GSMEM  (2*GSTAGE)         // 73728

template<int MODE>
__global__ void __launch_bounds__(128, 3)
gemm_mma(const float* __restrict__ bq, const float* __restrict__ bk,
         const float* __restrict__ bv, const float* __restrict__ bo,
         float* __restrict__ out)
{
    extern __shared__ char smem[];
    const uint32_t sb = smem_u32(smem);

    const int tid  = threadIdx.x;
    const int wid  = tid >> 5;
    const int lane = tid & 31;
    const int gid  = lane >> 2;
    const int tig  = lane & 3;
    const int am   = (wid & 1) * 64;
    const int bn   = (wid >> 1) * 64;

    const int m0  = blockIdx.y * 128;
    const int n0g = blockIdx.x * 128;

    int which = 3, nn0 = n0g;
    const float* bias = bo;
    if (MODE == 0) {
        which = n0g >> 10;                // 128-tile never straddles 1024
        nn0   = n0g & 1023;
        bias  = (which == 0) ? bq : (which == 1 ? bk : bv);
    }
    const float* A = (MODE == 0) ? g_qr : g_ctx;
    const float* W = g_wr + (size_t)which * DMODEL * DMODEL;

    float acc[4][8][4];
    #pragma unroll
    for (int mt = 0; mt < 4; mt++)
        #pragma unroll
        for (int nt = 0; nt < 8; nt++)
            #pragma unroll
            for (int c = 0; c < 4; c++) acc[mt][nt][c] = 0.f;

    auto load_chunk = [&](int c, int st) {
        const uint32_t sa = sb + st * GSTAGE;
        #pragma unroll
        for (int it = 0; it < 8; it++) {
            int lin = tid + it * 128;
            int row = lin >> 3, ch = lin & 7;
            cpasync16(sa + row*GROWB + ch*16,
                      A + (size_t)(m0 + row) * DMODEL + c*GKC + ch*4);
        }
        const uint32_t sB = sa + GTILEB;
        #pragma unroll
        for (int it = 0; it < 8; it++) {
            int lin = tid + it * 128;
            int row = lin >> 3, ch = lin & 7;
            cpasync16(sB + row*GROWB + ch*16,
                      W + (size_t)(nn0 + row) * DMODEL + c*GKC + ch*4);
        }
        CP_COMMIT();
    };

    load_chunk(0, 0);

    for (int i = 0; i < GNCH; i++) {
        __syncthreads();                      // stage (i+1)&1 free for overwrite
        if (i + 1 < GNCH) { load_chunk(i + 1, (i + 1) & 1); CP_WAIT(1); }
        else              { CP_WAIT(0); }
        __syncthreads();                      // stage i visible to all warps

        const unsigned* Au = (const unsigned*)(smem + (i & 1) * GSTAGE);
        const unsigned* Bu = (const unsigned*)(smem + (i & 1) * GSTAGE + GTILEB);
        #pragma unroll
        for (int ks = 0; ks < 4; ks++) {
            const int kk = ks * 8;
            unsigned a[4][4];
            #pragma unroll
            for (int mt = 0; mt < 4; mt++) {
                int r = am + mt*16 + gid;
                a[mt][0] = Au[r*36       + kk + tig];
                a[mt][1] = Au[(r+8)*36   + kk + tig];
                a[mt][2] = Au[r*36       + kk + tig + 4];
                a[mt][3] = Au[(r+8)*36   + kk + tig + 4];
            }
            unsigned bf[8][2];
            #pragma unroll
            for (int nt = 0; nt < 8; nt++) {
                int nr = bn + nt*8 + gid;
                bf[nt][0] = Bu[nr*36 + kk + tig];
                bf[nt][1] = Bu[nr*36 + kk + tig + 4];
            }
            #pragma unroll
            for (int mt = 0; mt < 4; mt++)
                #pragma unroll
                for (int nt = 0; nt < 8; nt++)
                    mma8(acc[mt][nt], a[mt], bf[nt]);
        }
    }

    // epilogue
    #pragma unroll
    for (int mt = 0; mt < 4; mt++) {
        int mrow = m0 + am + mt*16 + gid;
        #pragma unroll
        for (int nt = 0; nt < 8; nt++) {
            int nn = nn0 + bn + nt*8 + 2*tig;
            float2 bia = *(const float2*)&bias[nn];
            if (MODE == 0) {
                float2 v0, v1;
                v0.x = tf32rf(acc[mt][nt][0] + bia.x);  v0.y = tf32rf(acc[mt][nt][1] + bia.y);
                v1.x = tf32rf(acc[mt][nt][2] + bia.x);  v1.y = tf32rf(acc[mt][nt][3] + bia.y);
                float* dst = (which == 0) ? g_q : (which == 1 ? g_k : g_v);
                int hh = nn >> 6, dd = nn & 63;
                int bidx = mrow >> 11, t = mrow & 2047;
                *(float2*)&dst[((size_t)((bidx*NH + hh)*TT + t)) * DK + dd]     = v0;
                *(float2*)&dst[((size_t)((bidx*NH + hh)*TT + t + 8)) * DK + dd] = v1;
            } else {
                float2 v0, v1;
                v0.x = acc[mt][nt][0] + bia.x;  v0.y = acc[mt][nt][1] + bia.y;
                v1.x = acc[mt][nt][2] + bia.x;  v1.y = acc[mt][nt][3] + bia.y;
                *(float2*)&out[(size_t)mrow * DMODEL + nn]     = v0;
                *(float2*)&out[(size_t)(mrow+8) * DMODEL + nn] = v1;
            }
        }
    }
}

// ---------------------------------------------------------------------------
// Causal flash attention, tf32 mma.sync, 32-row KV tiles double-buffered.
// One block = (64-row q tile, h, b), 128 threads (4 warps), warp owns 16 rows.
// Smem 44KB -> 5 blocks/SM (20 warps). K stride 68 (bank perm 4*gid+tig),
// V stride 72 (perm 8*tig+gid), P stride 36 (perm 4*gid+tig).
// ---------------------------------------------------------------------------
#define AKROWS 32
#define AKB   (AKROWS*68*4)       // 8704
#define AVB   (AKROWS*72*4)       // 9216
#define ASTG  (AKB+AVB)           // 17920
#define APOFF (2*ASTG)            // Ps at 35840
#define ASMEM (APOFF + 64*36*4)   // 45056

__global__ void __launch_bounds__(128, 5)
attn_tf32()
{
    extern __shared__ char smem[];
    const uint32_t sb = smem_u32(smem);

    const int qt  = 31 - (int)blockIdx.x;   // big causal tiles first
    const int h   = blockIdx.y;
    const int b   = blockIdx.z;
    const int tid  = threadIdx.x;
    const int warp = tid >> 5;
    const int lane = tid & 31;
    const int gid  = lane >> 2;
    const int tig  = lane & 3;

    const size_t base = (size_t)(b*NH + h) * TT * DK;
    const float* Qg = g_q + base;
    const float* Kg = g_k + base;
    const float* Vg = g_v + base;

    unsigned* Ps = (unsigned*)(smem + APOFF);

    // Q fragments (scaled by 1/8 — exact on tf32-exact values)
    unsigned qf[8][4];
    {
        const int r0 = qt*64 + warp*16 + gid;
        #pragma unroll
        for (int ks = 0; ks < 8; ks++) {
            qf[ks][0] = tf32r(Qg[(size_t)r0*DK     + ks*8 + tig]     * 0.125f);
            qf[ks][1] = tf32r(Qg[(size_t)(r0+8)*DK + ks*8 + tig]     * 0.125f);
            qf[ks][2] = tf32r(Qg[(size_t)r0*DK     + ks*8 + tig + 4] * 0.125f);
            qf[ks][3] = tf32r(Qg[(size_t)(r0+8)*DK + ks*8 + tig + 4] * 0.125f);
        }
    }

    float o[8][4];
    #pragma unroll
    for (int nt = 0; nt < 8; nt++)
        #pragma unroll
        for (int c = 0; c < 4; c++) o[nt][c] = 0.f;
    float m0r = -1e30f, m1r = -1e30f, l0 = 0.f, l1 = 0.f;

    const int prow0 = warp*16 + gid;
    const int prow1 = prow0 + 8;

    // 32 KV rows per load: 128 threads x 16B covers 2048 floats = 32x64 each
    auto load_kv = [&](int j, int st) {
        const uint32_t sK = sb + st * ASTG;
        const uint32_t sV = sK + AKB;
        #pragma unroll
        for (int it = 0; it < 4; it++) {
            int lin = tid + it * 128;
            int row = lin >> 4, ch = lin & 15;
            cpasync16(sK + row*272 + ch*16, Kg + (size_t)(j*AKROWS + row)*DK + ch*4);
            cpasync16(sV + row*288 + ch*16, Vg + (size_t)(j*AKROWS + row)*DK + ch*4);
        }
        CP_COMMIT();
    };

    const int jmax = 2*qt + 1;
    load_kv(0, 0);

    for (int j = 0; j <= jmax; j++) {
        __syncthreads();                         // other stage free
        if (j < jmax) { load_kv(j + 1, (j + 1) & 1); CP_WAIT(1); }
        else          { CP_WAIT(0); }
        __syncthreads();                         // stage j visible

        const unsigned* Ks = (const unsigned*)(smem + (j & 1) * ASTG);
        const unsigned* Vs = (const unsigned*)(smem + (j & 1) * ASTG + AKB);

        // S = Q K^T : 16x32 per warp
        float s[4][4];
        #pragma unroll
        for (int nt = 0; nt < 4; nt++)
            #pragma unroll
            for (int c = 0; c < 4; c++) s[nt][c] = 0.f;

        #pragma unroll
        for (int ks = 0; ks < 8; ks++) {
            unsigned bf[2];
            #pragma unroll
            for (int nt = 0; nt < 4; nt++) {
                int tr = nt*8 + gid;
                bf[0] = Ks[tr*68 + ks*8 + tig];
                bf[1] = Ks[tr*68 + ks*8 + tig + 4];
                mma8(s[nt], qf[ks], bf);
            }
        }

        // causal mask on diagonal tiles (j = 2qt or 2qt+1)
        if (j >= 2*qt) {
            const int colbase = (j - 2*qt) * 32;
            const int r0l = warp*16 + gid;
            #pragma unroll
            for (int nt = 0; nt < 4; nt++) {
                int col = colbase + nt*8 + 2*tig;
                if (col     > r0l)     s[nt][0] = -1e30f;
                if (col + 1 > r0l)     s[nt][1] = -1e30f;
                if (col     > r0l + 8) s[nt][2] = -1e30f;
                if (col + 1 > r0l + 8) s[nt][3] = -1e30f;
            }
        }

        // online softmax
        float mx0 = -1e30f, mx1 = -1e30f;
        #pragma unroll
        for (int nt = 0; nt < 4; nt++) {
            mx0 = fmaxf(mx0, fmaxf(s[nt][0], s[nt][1]));
            mx1 = fmaxf(mx1, fmaxf(s[nt][2], s[nt][3]));
        }
        mx0 = fmaxf(mx0, __shfl_xor_sync(0xffffffffu, mx0, 1));
        mx0 = fmaxf(mx0, __shfl_xor_sync(0xffffffffu, mx0, 2));
        mx1 = fmaxf(mx1, __shfl_xor_sync(0xffffffffu, mx1, 1));
        mx1 = fmaxf(mx1, __shfl_xor_sync(0xffffffffu, mx1, 2));

        float nm0 = fmaxf(m0r, mx0), nm1 = fmaxf(m1r, mx1);
        float corr0 = __expf(m0r - nm0), corr1 = __expf(m1r - nm1);
        float rs0 = 0.f, rs1 = 0.f;
        #pragma unroll
        for (int nt = 0; nt < 4; nt++) {
            s[nt][0] = __expf(s[nt][0] - nm0);
            s[nt][1] = __expf(s[nt][1] - nm0);
            s[nt][2] = __expf(s[nt][2] - nm1);
            s[nt][3] = __expf(s[nt][3] - nm1);
            rs0 += s[nt][0] + s[nt][1];
            rs1 += s[nt][2] + s[nt][3];
        }
        rs0 += __shfl_xor_sync(0xffffffffu, rs0, 1);
        rs0 += __shfl_xor_sync(0xffffffffu, rs0, 2);
        rs1 += __shfl_xor_sync(0xffffffffu, rs1, 1);
        rs1 += __shfl_xor_sync(0xffffffffu, rs1, 2);
        l0 = l0 * corr0 + rs0;  m0r = nm0;
        l1 = l1 * corr1 + rs1;  m1r = nm1;
        #pragma unroll
        for (int nt = 0; nt < 8; nt++) {
            o[nt][0] *= corr0;  o[nt][1] *= corr0;
            o[nt][2] *= corr1;  o[nt][3] *= corr1;
        }

        // stage P (tf32) into this warp's private band (cols 0..31)
        __syncwarp();
        #pragma unroll
        for (int nt = 0; nt < 4; nt++) {
            uint2 p0; p0.x = tf32r(s[nt][0]); p0.y = tf32r(s[nt][1]);
            uint2 p1; p1.x = tf32r(s[nt][2]); p1.y = tf32r(s[nt][3]);
            *(uint2*)&Ps[prow0*36 + nt*8 + 2*tig] = p0;
            *(uint2*)&Ps[prow1*36 + nt*8 + 2*tig] = p1;
        }
        __syncwarp();

        // O += P V : k-dim 32 (4 k8 steps)
        #pragma unroll
        for (int ks = 0; ks < 4; ks++) {
            unsigned pa[4];
            pa[0] = Ps[prow0*36 + ks*8 + tig];
            pa[1] = Ps[prow1*36 + ks*8 + tig];
            pa[2] = Ps[prow0*36 + ks*8 + tig + 4];
            pa[3] = Ps[prow1*36 + ks*8 + tig + 4];
            unsigned vb[2];
            #pragma unroll
            for (int nt = 0; nt < 8; nt++) {
                vb[0] = Vs[(ks*8 + tig)*72     + nt*8 + gid];
                vb[1] = Vs[(ks*8 + tig + 4)*72 + nt*8 + gid];
                mma8(o[nt], pa, vb);
            }
        }
    }

    // epilogue: ctx (tf32-rounded so the Wo GEMM can consume raw bits)
    const float inv0 = 1.f / l0, inv1 = 1.f / l1;
    const int grow0 = b*TT + qt*64 + warp*16 + gid;
    #pragma unroll
    for (int nt = 0; nt < 8; nt++) {
        int dd = h*DK + nt*8 + 2*tig;
        float2 w0; w0.x = tf32rf(o[nt][0]*inv0); w0.y = tf32rf(o[nt][1]*inv0);
        float2 w1; w1.x = tf32rf(o[nt][2]*inv1); w1.y = tf32rf(o[nt][3]*inv1);
        *(float2*)&g_ctx[(size_t)grow0*DMODEL + dd]     = w0;
        *(float2*)&g_ctx[(size_t)(grow0+8)*DMODEL + dd] = w1;
    }
}

// ---------------------------------------------------------------------------

extern "C" void kernel_launch(void* const* d_in, const int* in_sizes, int n_in,
                              void* d_out, int out_size)
{
    const float* q  = (const float*)d_in[0];
    // d_in[1] = mask (causal by construction; applied analytically)
    const float* Wq = (const float*)d_in[2];
    const float* bq = (const float*)d_in[3];
    const float* Wk = (const float*)d_in[4];
    const float* bk = (const float*)d_in[5];
    const float* Wv = (const float*)d_in[6];
    const float* bv = (const float*)d_in[7];
    const float* Wo = (const float*)d_in[8];
    const float* bo = (const float*)d_in[9];
    float* out = (float*)d_out;

    // 0) pre-round operands to tf32 (rna)
    round_w_kernel<<<1024, 256>>>(Wq, Wk, Wv, Wo);
    round_q_kernel<<<8192, 256>>>(q);

    // 1) fused QKV projection
    cudaFuncSetAttribute(gemm_mma<0>, cudaFuncAttributeMaxDynamicSharedMemorySize, GSMEM);
    gemm_mma<0><<<dim3(24, 64), 128, GSMEM>>>(bq, bk, bv, bo, nullptr);

    // 2) causal flash attention
    cudaFuncSetAttribute(attn_tf32, cudaFuncAttributeMaxDynamicSharedMemorySize, ASMEM);
    attn_tf32<<<dim3(32, NH, BB), 128, ASMEM>>>();

    // 3) output projection
    cudaFuncSetAttribute(gemm_mma<1>, cudaFuncAttributeMaxDynamicSharedMemorySize, GSMEM);
    gemm_mma<1><<<dim3(8, 64), 128, GSMEM>>>(bq, bk, bv, bo, out);
}

// round 12
// speedup vs baseline: 4.6519x; 1.0707x over previous
#include <cuda_runtime.h>
#include <math.h>
#include <stdint.h>

#define DMODEL 1024
#define NH 16
#define DK 64
#define BB 4
#define TT 2048
#define MTOT (BB*TT)   // 8192

// Scratch (alloc-free rule: __device__ globals)
__device__ float g_q[BB*NH*TT*DK];       // (b,h,t,d)   tf32-exact, unpacked
__device__ float g_k[BB*NH*TT*DK];       // (b,h,t,dpacked)  tf32-exact
__device__ float g_v[BB*NH*DK*TT];       // (b,h,d,tpacked)  tf32-exact (TRANSPOSED)
__device__ float g_ctx[MTOT*DMODEL];     // (b,t,h*dk)  tf32-exact
__device__ float g_qr[MTOT*DMODEL];      // q pre-rounded to tf32
__device__ float g_wr[4*DMODEL*DMODEL];  // Wq|Wk|Wv|Wo pre-rounded to tf32

// ---------------------------------------------------------------------------
// helpers
// ---------------------------------------------------------------------------
__device__ __forceinline__ unsigned tf32r(float f) {
    unsigned r;
    asm("cvt.rna.tf32.f32 %0, %1;" : "=r"(r) : "f"(f));
    return r;
}
__device__ __forceinline__ float tf32rf(float f) { return __uint_as_float(tf32r(f)); }

// fragment-pair packing within 8-element groups: slot 2*(x&3)+((x>>2)&1).
// load of slots (2t, 2t+1) yields elements (t, t+4) -> one LDS.64 per mma frag.
__device__ __forceinline__ int packi(int x) {
    return (x & ~7) | (((x & 3) << 1) | ((x >> 2) & 1));
}

__device__ __forceinline__ uint32_t smem_u32(const void* p) {
    uint32_t a;
    asm("{ .reg .u64 t; cvta.to.shared.u64 t, %1; cvt.u32.u64 %0, t; }" : "=r"(a) : "l"(p));
    return a;
}
__device__ __forceinline__ void cpasync16(uint32_t saddr, const void* g) {
    asm volatile("cp.async.cg.shared.global [%0], [%1], 16;" :: "r"(saddr), "l"(g));
}
#define CP_COMMIT()  asm volatile("cp.async.commit_group;" ::: "memory")
#define CP_WAIT(n)   asm volatile("cp.async.wait_group %0;" :: "n"(n) : "memory")

__device__ __forceinline__ void mma8(float c[4], const unsigned a[4], const unsigned b[2]) {
    asm volatile(
        "mma.sync.aligned.m16n8k8.row.col.f32.tf32.tf32.f32 "
        "{%0,%1,%2,%3}, {%4,%5,%6,%7}, {%8,%9}, {%0,%1,%2,%3};"
        : "+f"(c[0]), "+f"(c[1]), "+f"(c[2]), "+f"(c[3])
        : "r"(a[0]), "r"(a[1]), "r"(a[2]), "r"(a[3]), "r"(b[0]), "r"(b[1]));
}

// ---------------------------------------------------------------------------
// pre-round passes (rna -> tf32-exact fp32)
// ---------------------------------------------------------------------------
__global__ void __launch_bounds__(256)
round_w_kernel(const float* __restrict__ wq, const float* __restrict__ wk,
               const float* __restrict__ wv, const float* __restrict__ wo)
{
    const int i = blockIdx.x * 256 + threadIdx.x;
    const float4* src[4] = { (const float4*)wq, (const float4*)wk,
                             (const float4*)wv, (const float4*)wo };
    float4* dst = (float4*)g_wr;
    #pragma unroll
    for (int m = 0; m < 4; m++) {
        float4 v = src[m][i];
        v.x = tf32rf(v.x); v.y = tf32rf(v.y); v.z = tf32rf(v.z); v.w = tf32rf(v.w);
        dst[(size_t)m * (DMODEL*DMODEL/4) + i] = v;
    }
}
__global__ void __launch_bounds__(256)
round_q_kernel(const float* __restrict__ q)
{
    const int i = blockIdx.x * 256 + threadIdx.x;
    float4 v = ((const float4*)q)[i];
    v.x = tf32rf(v.x); v.y = tf32rf(v.y); v.z = tf32rf(v.z); v.w = tf32rf(v.w);
    ((float4*)g_qr)[i] = v;
}

// ---------------------------------------------------------------------------
// tf32 mma.sync GEMM (unchanged from round 9 except MODE 0 K/V scatter layouts)
// Block 128x128, 128 threads (4 warps, 2x2), warp tile 64x64, KC=32,
// 2-stage cp.async pipeline (72KB smem -> 3 blocks/SM).
// ---------------------------------------------------------------------------
#define GKC    32
#define GNCH   (DMODEL/GKC)       // 32
#define GROWB  144                // 36 floats
#define GTILEB (128*GROWB)        // 18432
#define GSTAGE (2*GTILEB)         // A + B = 36864
#define GSMEM  (2*GSTAGE)         // 73728

template<int MODE>
__global__ void __launch_bounds__(128, 3)
gemm_mma(const float* __restrict__ bq, const float* __restrict__ bk,
         const float* __restrict__ bv, const float* __restrict__ bo,
         float* __restrict__ out)
{
    extern __shared__ char smem[];
    const uint32_t sb = smem_u32(smem);

    const int tid  = threadIdx.x;
    const int wid  = tid >> 5;
    const int lane = tid & 31;
    const int gid  = lane >> 2;
    const int tig  = lane & 3;
    const int am   = (wid & 1) * 64;
    const int bn   = (wid >> 1) * 64;

    const int m0  = blockIdx.y * 128;
    const int n0g = blockIdx.x * 128;

    int which = 3, nn0 = n0g;
    const float* bias = bo;
    if (MODE == 0) {
        which = n0g >> 10;                // 128-tile never straddles 1024
        nn0   = n0g & 1023;
        bias  = (which == 0) ? bq : (which == 1 ? bk : bv);
    }
    const float* A = (MODE == 0) ? g_qr : g_ctx;
    const float* W = g_wr + (size_t)which * DMODEL * DMODEL;

    float acc[4][8][4];
    #pragma unroll
    for (int mt = 0; mt < 4; mt++)
        #pragma unroll
        for (int nt = 0; nt < 8; nt++)
            #pragma unroll
            for (int c = 0; c < 4; c++) acc[mt][nt][c] = 0.f;

    auto load_chunk = [&](int c, int st) {
        const uint32_t sa = sb + st * GSTAGE;
        #pragma unroll
        for (int it = 0; it < 8; it++) {
            int lin = tid + it * 128;
            int row = lin >> 3, ch = lin & 7;
            cpasync16(sa + row*GROWB + ch*16,
                      A + (size_t)(m0 + row) * DMODEL + c*GKC + ch*4);
        }
        const uint32_t sB = sa + GTILEB;
        #pragma unroll
        for (int it = 0; it < 8; it++) {
            int lin = tid + it * 128;
            int row = lin >> 3, ch = lin & 7;
            cpasync16(sB + row*GROWB + ch*16,
                      W + (size_t)(nn0 + row) * DMODEL + c*GKC + ch*4);
        }
        CP_COMMIT();
    };

    load_chunk(0, 0);

    for (int i = 0; i < GNCH; i++) {
        __syncthreads();                      // stage (i+1)&1 free for overwrite
        if (i + 1 < GNCH) { load_chunk(i + 1, (i + 1) & 1); CP_WAIT(1); }
        else              { CP_WAIT(0); }
        __syncthreads();                      // stage i visible to all warps

        const unsigned* Au = (const unsigned*)(smem + (i & 1) * GSTAGE);
        const unsigned* Bu = (const unsigned*)(smem + (i & 1) * GSTAGE + GTILEB);
        #pragma unroll
        for (int ks = 0; ks < 4; ks++) {
            const int kk = ks * 8;
            unsigned a[4][4];
            #pragma unroll
            for (int mt = 0; mt < 4; mt++) {
                int r = am + mt*16 + gid;
                a[mt][0] = Au[r*36       + kk + tig];
                a[mt][1] = Au[(r+8)*36   + kk + tig];
                a[mt][2] = Au[r*36       + kk + tig + 4];
                a[mt][3] = Au[(r+8)*36   + kk + tig + 4];
            }
            unsigned bf[8][2];
            #pragma unroll
            for (int nt = 0; nt < 8; nt++) {
                int nr = bn + nt*8 + gid;
                bf[nt][0] = Bu[nr*36 + kk + tig];
                bf[nt][1] = Bu[nr*36 + kk + tig + 4];
            }
            #pragma unroll
            for (int mt = 0; mt < 4; mt++)
                #pragma unroll
                for (int nt = 0; nt < 8; nt++)
                    mma8(acc[mt][nt], a[mt], bf[nt]);
        }
    }

    // epilogue
    #pragma unroll
    for (int mt = 0; mt < 4; mt++) {
        int mrow = m0 + am + mt*16 + gid;
        #pragma unroll
        for (int nt = 0; nt < 8; nt++) {
            int nn = nn0 + bn + nt*8 + 2*tig;
            float2 bia = *(const float2*)&bias[nn];
            if (MODE == 0) {
                float vx0 = tf32rf(acc[mt][nt][0] + bia.x);
                float vy0 = tf32rf(acc[mt][nt][1] + bia.y);
                float vx1 = tf32rf(acc[mt][nt][2] + bia.x);
                float vy1 = tf32rf(acc[mt][nt][3] + bia.y);
                int hh = nn >> 6, dd = nn & 63;
                int bidx = mrow >> 11, t = mrow & 2047;
                if (which == 0) {
                    float2 v0 = make_float2(vx0, vy0), v1 = make_float2(vx1, vy1);
                    *(float2*)&g_q[((size_t)((bidx*NH + hh)*TT + t)) * DK + dd]     = v0;
                    *(float2*)&g_q[((size_t)((bidx*NH + hh)*TT + t + 8)) * DK + dd] = v1;
                } else if (which == 1) {
                    // packed-d layout: slot packi(d) within row t
                    int p0 = packi(dd), p1 = packi(dd + 1);
                    size_t rb = ((size_t)((bidx*NH + hh)*TT + t)) * DK;
                    g_k[rb + p0]          = vx0;
                    g_k[rb + p1]          = vy0;
                    g_k[rb + 8*DK + p0]   = vx1;
                    g_k[rb + 8*DK + p1]   = vy1;
                } else {
                    // transposed (d,t) with packed-t layout
                    size_t db = (size_t)((bidx*NH + hh)) * DK;
                    int pt0 = packi(t);              // packi(t+8) = pt0 + 8
                    g_v[(db + dd    )*TT + pt0]     = vx0;
                    g_v[(db + dd + 1)*TT + pt0]     = vy0;
                    g_v[(db + dd    )*TT + pt0 + 8] = vx1;
                    g_v[(db + dd + 1)*TT + pt0 + 8] = vy1;
                }
            } else {
                float2 v0, v1;
                v0.x = acc[mt][nt][0] + bia.x;  v0.y = acc[mt][nt][1] + bia.y;
                v1.x = acc[mt][nt][2] + bia.x;  v1.y = acc[mt][nt][3] + bia.y;
                *(float2*)&out[(size_t)mrow * DMODEL + nn]     = v0;
                *(float2*)&out[(size_t)(mrow+8) * DMODEL + nn] = v1;
            }
        }
    }
}

// ---------------------------------------------------------------------------
// Causal flash attention, tf32 mma.sync, 64-row KV tiles double-buffered.
// One block = (64-row q tile, h, b), 128 threads (4 warps), warp owns 16 rows.
// K: (t, packed-d) -> B-frag pair = one LDS.64.  V: (d, packed-t) transposed
// -> PV B-frag pair = one LDS.64.  K/V smem stride 72 floats (==8 mod 32:
// half-warp 8B footprints {8g+2t} tile all 32 banks, conflict-free).
// Smem 89KB -> 2 blocks/SM. P stride 68 (round-6 verified pattern).
// ---------------------------------------------------------------------------
#define AKB   (64*72*4)           // 18432
#define AVB   (64*72*4)           // 18432
#define ASTG  (AKB+AVB)           // 36864
#define APOFF (2*ASTG)            // Ps at 73728
#define ASMEM (APOFF + 64*68*4)   // 91136

__global__ void __launch_bounds__(128, 2)
attn_tf32()
{
    extern __shared__ char smem[];
    const uint32_t sb = smem_u32(smem);

    const int qt  = 31 - (int)blockIdx.x;   // big causal tiles first
    const int h   = blockIdx.y;
    const int b   = blockIdx.z;
    const int tid  = threadIdx.x;
    const int warp = tid >> 5;
    const int lane = tid & 31;
    const int gid  = lane >> 2;
    const int tig  = lane & 3;

    const float* Qg = g_q + (size_t)(b*NH + h) * TT * DK;
    const float* Kg = g_k + (size_t)(b*NH + h) * TT * DK;
    const float* Vg = g_v + (size_t)(b*NH + h) * DK * TT;   // (d, packed-t)

    unsigned* Ps = (unsigned*)(smem + APOFF);

    // Q fragments (scaled by 1/8 — exact on tf32-exact values)
    unsigned qf[8][4];
    {
        const int r0 = qt*64 + warp*16 + gid;
        #pragma unroll
        for (int ks = 0; ks < 8; ks++) {
            qf[ks][0] = tf32r(Qg[(size_t)r0*DK     + ks*8 + tig]     * 0.125f);
            qf[ks][1] = tf32r(Qg[(size_t)(r0+8)*DK + ks*8 + tig]     * 0.125f);
            qf[ks][2] = tf32r(Qg[(size_t)r0*DK     + ks*8 + tig + 4] * 0.125f);
            qf[ks][3] = tf32r(Qg[(size_t)(r0+8)*DK + ks*8 + tig + 4] * 0.125f);
        }
    }

    float o[8][4];
    #pragma unroll
    for (int nt = 0; nt < 8; nt++)
        #pragma unroll
        for (int c = 0; c < 4; c++) o[nt][c] = 0.f;
    float m0r = -1e30f, m1r = -1e30f, l0 = 0.f, l1 = 0.f;

    const int prow0 = warp*16 + gid;
    const int prow1 = prow0 + 8;

    // K tile: 64 rows t x 64 packed-d.  V tile: 64 rows d x 64 packed-t cols.
    auto load_kv = [&](int kt, int st) {
        const uint32_t sK = sb + st * ASTG;
        const uint32_t sV = sK + AKB;
        #pragma unroll
        for (int it = 0; it < 8; it++) {
            int lin = tid + it * 128;
            int row = lin >> 4, ch = lin & 15;
            cpasync16(sK + row*288 + ch*16, Kg + (size_t)(kt*64 + row)*DK + ch*4);
            cpasync16(sV + row*288 + ch*16, Vg + (size_t)row*TT + kt*64 + ch*4);
        }
        CP_COMMIT();
    };

    load_kv(0, 0);

    for (int kt = 0; kt <= qt; kt++) {
        __syncthreads();                         // other stage free
        if (kt < qt) { load_kv(kt + 1, (kt + 1) & 1); CP_WAIT(1); }
        else         { CP_WAIT(0); }
        __syncthreads();                         // stage kt visible

        const unsigned* Ks = (const unsigned*)(smem + (kt & 1) * ASTG);
        const unsigned* Vs = (const unsigned*)(smem + (kt & 1) * ASTG + AKB);

        // S = Q K^T : 16x64 per warp; B-frag pair via one LDS.64
        float s[8][4];
        #pragma unroll
        for (int nt = 0; nt < 8; nt++)
            #pragma unroll
            for (int c = 0; c < 4; c++) s[nt][c] = 0.f;

        #pragma unroll
        for (int ks = 0; ks < 8; ks++) {
            #pragma unroll
            for (int nt = 0; nt < 8; nt++) {
                int tr = nt*8 + gid;
                uint2 bf2 = *(const uint2*)&Ks[tr*72 + ks*8 + 2*tig];
                unsigned bf[2] = { bf2.x, bf2.y };
                mma8(s[nt], qf[ks], bf);
            }
        }

        if (kt == qt) {
            const int r0l = warp*16 + gid;
            #pragma unroll
            for (int nt = 0; nt < 8; nt++) {
                int col = nt*8 + 2*tig;
                if (col     > r0l)     s[nt][0] = -1e30f;
                if (col + 1 > r0l)     s[nt][1] = -1e30f;
                if (col     > r0l + 8) s[nt][2] = -1e30f;
                if (col + 1 > r0l + 8) s[nt][3] = -1e30f;
            }
        }

        // online softmax
        float mx0 = -1e30f, mx1 = -1e30f;
        #pragma unroll
        for (int nt = 0; nt < 8; nt++) {
            mx0 = fmaxf(mx0, fmaxf(s[nt][0], s[nt][1]));
            mx1 = fmaxf(mx1, fmaxf(s[nt][2], s[nt][3]));
        }
        mx0 = fmaxf(mx0, __shfl_xor_sync(0xffffffffu, mx0, 1));
        mx0 = fmaxf(mx0, __shfl_xor_sync(0xffffffffu, mx0, 2));
        mx1 = fmaxf(mx1, __shfl_xor_sync(0xffffffffu, mx1, 1));
        mx1 = fmaxf(mx1, __shfl_xor_sync(0xffffffffu, mx1, 2));

        float nm0 = fmaxf(m0r, mx0), nm1 = fmaxf(m1r, mx1);
        float corr0 = __expf(m0r - nm0), corr1 = __expf(m1r - nm1);
        float rs0 = 0.f, rs1 = 0.f;
        #pragma unroll
        for (int nt = 0; nt < 8; nt++) {
            s[nt][0] = __expf(s[nt][0] - nm0);
            s[nt][1] = __expf(s[nt][1] - nm0);
            s[nt][2] = __expf(s[nt][2] - nm1);
            s[nt][3] = __expf(s[nt][3] - nm1);
            rs0 += s[nt][0] + s[nt][1];
            rs1 += s[nt][2] + s[nt][3];
        }
        rs0 += __shfl_xor_sync(0xffffffffu, rs0, 1);
        rs0 += __shfl_xor_sync(0xffffffffu, rs0, 2);
        rs1 += __shfl_xor_sync(0xffffffffu, rs1, 1);
        rs1 += __shfl_xor_sync(0xffffffffu, rs1, 2);
        l0 = l0 * corr0 + rs0;  m0r = nm0;
        l1 = l1 * corr1 + rs1;  m1r = nm1;
        #pragma unroll
        for (int nt = 0; nt < 8; nt++) {
            o[nt][0] *= corr0;  o[nt][1] *= corr0;
            o[nt][2] *= corr1;  o[nt][3] *= corr1;
        }

        // stage P (tf32) into this warp's private band
        __syncwarp();
        #pragma unroll
        for (int nt = 0; nt < 8; nt++) {
            uint2 p0; p0.x = tf32r(s[nt][0]); p0.y = tf32r(s[nt][1]);
            uint2 p1; p1.x = tf32r(s[nt][2]); p1.y = tf32r(s[nt][3]);
            *(uint2*)&Ps[prow0*68 + nt*8 + 2*tig] = p0;
            *(uint2*)&Ps[prow1*68 + nt*8 + 2*tig] = p1;
        }
        __syncwarp();

        // O += P V : B-frag pair via one LDS.64 (transposed+packed V)
        #pragma unroll
        for (int ks = 0; ks < 8; ks++) {
            unsigned pa[4];
            pa[0] = Ps[prow0*68 + ks*8 + tig];
            pa[1] = Ps[prow1*68 + ks*8 + tig];
            pa[2] = Ps[prow0*68 + ks*8 + tig + 4];
            pa[3] = Ps[prow1*68 + ks*8 + tig + 4];
            #pragma unroll
            for (int nt = 0; nt < 8; nt++) {
                uint2 vb2 = *(const uint2*)&Vs[(nt*8 + gid)*72 + ks*8 + 2*tig];
                unsigned vb[2] = { vb2.x, vb2.y };
                mma8(o[nt], pa, vb);
            }
        }
    }

    // epilogue: ctx (tf32-rounded so the Wo GEMM can consume raw bits)
    const float inv0 = 1.f / l0, inv1 = 1.f / l1;
    const int grow0 = b*TT + qt*64 + warp*16 + gid;
    #pragma unroll
    for (int nt = 0; nt < 8; nt++) {
        int dd = h*DK + nt*8 + 2*tig;
        float2 w0; w0.x = tf32rf(o[nt][0]*inv0); w0.y = tf32rf(o[nt][1]*inv0);
        float2 w1; w1.x = tf32rf(o[nt][2]*inv1); w1.y = tf32rf(o[nt][3]*inv1);
        *(float2*)&g_ctx[(size_t)grow0*DMODEL + dd]     = w0;
        *(float2*)&g_ctx[(size_t)(grow0+8)*DMODEL + dd] = w1;
    }
}

// ---------------------------------------------------------------------------

extern "C" void kernel_launch(void* const* d_in, const int* in_sizes, int n_in,
                              void* d_out, int out_size)
{
    const float* q  = (const float*)d_in[0];
    // d_in[1] = mask (causal by construction; applied analytically)
    const float* Wq = (const float*)d_in[2];
    const float* bq = (const float*)d_in[3];
    const float* Wk = (const float*)d_in[4];
    const float* bk = (const float*)d_in[5];
    const float* Wv = (const float*)d_in[6];
    const float* bv = (const float*)d_in[7];
    const float* Wo = (const float*)d_in[8];
    const float* bo = (const float*)d_in[9];
    float* out = (float*)d_out;

    // 0) pre-round operands to tf32 (rna)
    round_w_kernel<<<1024, 256>>>(Wq, Wk, Wv, Wo);
    round_q_kernel<<<8192, 256>>>(q);

    // 1) fused QKV projection (K packed-d, V transposed+packed-t)
    cudaFuncSetAttribute(gemm_mma<0>, cudaFuncAttributeMaxDynamicSharedMemorySize, GSMEM);
    gemm_mma<0><<<dim3(24, 64), 128, GSMEM>>>(bq, bk, bv, bo, nullptr);

    // 2) causal flash attention (LDS.64 fragment loads)
    cudaFuncSetAttribute(attn_tf32, cudaFuncAttributeMaxDynamicSharedMemorySize, ASMEM);
    attn_tf32<<<dim3(32, NH, BB), 128, ASMEM>>>();

    // 3) output projection
    cudaFuncSetAttribute(gemm_mma<1>, cudaFuncAttributeMaxDynamicSharedMemorySize, GSMEM);
    gemm_mma<1><<<dim3(8, 64), 128, GSMEM>>>(bq, bk, bv, bo, out);
}

// round 17
// speedup vs baseline: 4.7624x; 1.0238x over previous
#include <cuda_runtime.h>
#include <math.h>
#include <stdint.h>

#define DMODEL 1024
#define NH 16
#define DK 64
#define BB 4
#define TT 2048
#define MTOT (BB*TT)   // 8192

// Scratch (alloc-free rule: __device__ globals)
__device__ float g_q[BB*NH*TT*DK];       // (b,h,t,d)   tf32-exact, unpacked
__device__ float g_k[BB*NH*TT*DK];       // (b,h,t,dpacked)  tf32-exact
__device__ float g_v[BB*NH*DK*TT];       // (b,h,d,tpacked)  tf32-exact (TRANSPOSED)
__device__ float g_ctx[MTOT*DMODEL];     // (b,t,h*dk)  tf32-exact
__device__ float g_qr[MTOT*DMODEL];      // q pre-rounded to tf32
__device__ float g_wr[4*DMODEL*DMODEL];  // Wq|Wk|Wv|Wo pre-rounded to tf32

// ---------------------------------------------------------------------------
// helpers
// ---------------------------------------------------------------------------
__device__ __forceinline__ unsigned tf32r(float f) {
    unsigned r;
    asm("cvt.rna.tf32.f32 %0, %1;" : "=r"(r) : "f"(f));
    return r;
}
__device__ __forceinline__ float tf32rf(float f) { return __uint_as_float(tf32r(f)); }

// fragment-pair packing within 8-element groups: slot 2*(x&3)+((x>>2)&1).
// load of slots (2t, 2t+1) yields elements (t, t+4) -> one LDS.64 per mma frag.
__device__ __forceinline__ int packi(int x) {
    return (x & ~7) | (((x & 3) << 1) | ((x >> 2) & 1));
}

__device__ __forceinline__ uint32_t smem_u32(const void* p) {
    uint32_t a;
    asm("{ .reg .u64 t; cvta.to.shared.u64 t, %1; cvt.u32.u64 %0, t; }" : "=r"(a) : "l"(p));
    return a;
}
__device__ __forceinline__ void cpasync16(uint32_t saddr, const void* g) {
    asm volatile("cp.async.cg.shared.global [%0], [%1], 16;" :: "r"(saddr), "l"(g));
}
#define CP_COMMIT()  asm volatile("cp.async.commit_group;" ::: "memory")
#define CP_WAIT(n)   asm volatile("cp.async.wait_group %0;" :: "n"(n) : "memory")

__device__ __forceinline__ void mma8(float c[4], const unsigned a[4], const unsigned b[2]) {
    asm volatile(
        "mma.sync.aligned.m16n8k8.row.col.f32.tf32.tf32.f32 "
        "{%0,%1,%2,%3}, {%4,%5,%6,%7}, {%8,%9}, {%0,%1,%2,%3};"
        : "+f"(c[0]), "+f"(c[1]), "+f"(c[2]), "+f"(c[3])
        : "r"(a[0]), "r"(a[1]), "r"(a[2]), "r"(a[3]), "r"(b[0]), "r"(b[1]));
}

// ---------------------------------------------------------------------------
// pre-round passes (rna -> tf32-exact fp32)
// ---------------------------------------------------------------------------
__global__ void __launch_bounds__(256)
round_w_kernel(const float* __restrict__ wq, const float* __restrict__ wk,
               const float* __restrict__ wv, const float* __restrict__ wo)
{
    const int i = blockIdx.x * 256 + threadIdx.x;
    const float4* src[4] = { (const float4*)wq, (const float4*)wk,
                             (const float4*)wv, (const float4*)wo };
    float4* dst = (float4*)g_wr;
    #pragma unroll
    for (int m = 0; m < 4; m++) {
        float4 v = src[m][i];
        v.x = tf32rf(v.x); v.y = tf32rf(v.y); v.z = tf32rf(v.z); v.w = tf32rf(v.w);
        dst[(size_t)m * (DMODEL*DMODEL/4) + i] = v;
    }
}
__global__ void __launch_bounds__(256)
round_q_kernel(const float* __restrict__ q)
{
    const int i = blockIdx.x * 256 + threadIdx.x;
    float4 v = ((const float4*)q)[i];
    v.x = tf32rf(v.x); v.y = tf32rf(v.y); v.z = tf32rf(v.z); v.w = tf32rf(v.w);
    ((float4*)g_qr)[i] = v;
}

// ---------------------------------------------------------------------------
// tf32 mma.sync GEMM (unchanged measured round-9/12 config)
// Block 128x128, 128 threads (4 warps, 2x2), warp tile 64x64, KC=32,
// 2-stage cp.async pipeline (72KB smem -> 3 blocks/SM).
// ---------------------------------------------------------------------------
#define GKC    32
#define GNCH   (DMODEL/GKC)       // 32
#define GROWB  144                // 36 floats
#define GTILEB (128*GROWB)        // 18432
#define GSTAGE (2*GTILEB)         // A + B = 36864
#define GSMEM  (2*GSTAGE)         // 73728

template<int MODE>
__global__ void __launch_bounds__(128, 3)
gemm_mma(const float* __restrict__ bq, const float* __restrict__ bk,
         const float* __restrict__ bv, const float* __restrict__ bo,
         float* __restrict__ out)
{
    extern __shared__ char smem[];
    const uint32_t sb = smem_u32(smem);

    const int tid  = threadIdx.x;
    const int wid  = tid >> 5;
    const int lane = tid & 31;
    const int gid  = lane >> 2;
    const int tig  = lane & 3;
    const int am   = (wid & 1) * 64;
    const int bn   = (wid >> 1) * 64;

    const int m0  = blockIdx.y * 128;
    const int n0g = blockIdx.x * 128;

    int which = 3, nn0 = n0g;
    const float* bias = bo;
    if (MODE == 0) {
        which = n0g >> 10;                // 128-tile never straddles 1024
        nn0   = n0g & 1023;
        bias  = (which == 0) ? bq : (which == 1 ? bk : bv);
    }
    const float* A = (MODE == 0) ? g_qr : g_ctx;
    const float* W = g_wr + (size_t)which * DMODEL * DMODEL;

    float acc[4][8][4];
    #pragma unroll
    for (int mt = 0; mt < 4; mt++)
        #pragma unroll
        for (int nt = 0; nt < 8; nt++)
            #pragma unroll
            for (int c = 0; c < 4; c++) acc[mt][nt][c] = 0.f;

    auto load_chunk = [&](int c, int st) {
        const uint32_t sa = sb + st * GSTAGE;
        #pragma unroll
        for (int it = 0; it < 8; it++) {
            int lin = tid + it * 128;
            int row = lin >> 3, ch = lin & 7;
            cpasync16(sa + row*GROWB + ch*16,
                      A + (size_t)(m0 + row) * DMODEL + c*GKC + ch*4);
        }
        const uint32_t sB = sa + GTILEB;
        #pragma unroll
        for (int it = 0; it < 8; it++) {
            int lin = tid + it * 128;
            int row = lin >> 3, ch = lin & 7;
            cpasync16(sB + row*GROWB + ch*16,
                      W + (size_t)(nn0 + row) * DMODEL + c*GKC + ch*4);
        }
        CP_COMMIT();
    };

    load_chunk(0, 0);

    for (int i = 0; i < GNCH; i++) {
        __syncthreads();                      // stage (i+1)&1 free for overwrite
        if (i + 1 < GNCH) { load_chunk(i + 1, (i + 1) & 1); CP_WAIT(1); }
        else              { CP_WAIT(0); }
        __syncthreads();                      // stage i visible to all warps

        const unsigned* Au = (const unsigned*)(smem + (i & 1) * GSTAGE);
        const unsigned* Bu = (const unsigned*)(smem + (i & 1) * GSTAGE + GTILEB);
        #pragma unroll
        for (int ks = 0; ks < 4; ks++) {
            const int kk = ks * 8;
            unsigned a[4][4];
            #pragma unroll
            for (int mt = 0; mt < 4; mt++) {
                int r = am + mt*16 + gid;
                a[mt][0] = Au[r*36       + kk + tig];
                a[mt][1] = Au[(r+8)*36   + kk + tig];
                a[mt][2] = Au[r*36       + kk + tig + 4];
                a[mt][3] = Au[(r+8)*36   + kk + tig + 4];
            }
            unsigned bf[8][2];
            #pragma unroll
            for (int nt = 0; nt < 8; nt++) {
                int nr = bn + nt*8 + gid;
                bf[nt][0] = Bu[nr*36 + kk + tig];
                bf[nt][1] = Bu[nr*36 + kk + tig + 4];
            }
            #pragma unroll
            for (int mt = 0; mt < 4; mt++)
                #pragma unroll
                for (int nt = 0; nt < 8; nt++)
                    mma8(acc[mt][nt], a[mt], bf[nt]);
        }
    }

    // epilogue
    #pragma unroll
    for (int mt = 0; mt < 4; mt++) {
        int mrow = m0 + am + mt*16 + gid;
        #pragma unroll
        for (int nt = 0; nt < 8; nt++) {
            int nn = nn0 + bn + nt*8 + 2*tig;
            float2 bia = *(const float2*)&bias[nn];
            if (MODE == 0) {
                float vx0 = tf32rf(acc[mt][nt][0] + bia.x);
                float vy0 = tf32rf(acc[mt][nt][1] + bia.y);
                float vx1 = tf32rf(acc[mt][nt][2] + bia.x);
                float vy1 = tf32rf(acc[mt][nt][3] + bia.y);
                int hh = nn >> 6, dd = nn & 63;
                int bidx = mrow >> 11, t = mrow & 2047;
                if (which == 0) {
                    float2 v0 = make_float2(vx0, vy0), v1 = make_float2(vx1, vy1);
                    *(float2*)&g_q[((size_t)((bidx*NH + hh)*TT + t)) * DK + dd]     = v0;
                    *(float2*)&g_q[((size_t)((bidx*NH + hh)*TT + t + 8)) * DK + dd] = v1;
                } else if (which == 1) {
                    // packed-d layout: slot packi(d) within row t
                    int p0 = packi(dd), p1 = packi(dd + 1);
                    size_t rb = ((size_t)((bidx*NH + hh)*TT + t)) * DK;
                    g_k[rb + p0]          = vx0;
                    g_k[rb + p1]          = vy0;
                    g_k[rb + 8*DK + p0]   = vx1;
                    g_k[rb + 8*DK + p1]   = vy1;
                } else {
                    // transposed (d,t) with packed-t layout
                    size_t db = (size_t)((bidx*NH + hh)) * DK;
                    int pt0 = packi(t);              // packi(t+8) = pt0 + 8
                    g_v[(db + dd    )*TT + pt0]     = vx0;
                    g_v[(db + dd + 1)*TT + pt0]     = vy0;
                    g_v[(db + dd    )*TT + pt0 + 8] = vx1;
                    g_v[(db + dd + 1)*TT + pt0 + 8] = vy1;
                }
            } else {
                float2 v0, v1;
                v0.x = acc[mt][nt][0] + bia.x;  v0.y = acc[mt][nt][1] + bia.y;
                v1.x = acc[mt][nt][2] + bia.x;  v1.y = acc[mt][nt][3] + bia.y;
                *(float2*)&out[(size_t)mrow * DMODEL + nn]     = v0;
                *(float2*)&out[(size_t)(mrow+8) * DMODEL + nn] = v1;
            }
        }
    }
}

// ---------------------------------------------------------------------------
// Causal flash attention, tf32 mma.sync, 64-row KV tiles double-buffered.
// One block = (64-row q tile, h, b), 128 threads (4 warps), warp owns 16 rows.
// K: (t, packed-d) -> S B-frag pair = one LDS.64.  V: (d, packed-t) -> PV
// B-frag pair = one LDS.64.  P REUSES the current-stage K region (K is dead
// after the S-loop; prefetch targets the other stage) -> smem 73.7KB ->
// 3 blocks/SM (12 warps). One extra __syncthreads guards the K->P overwrite.
// ---------------------------------------------------------------------------
#define AKB   (64*72*4)           // 18432
#define AVB   (64*72*4)           // 18432
#define ASTG  (AKB+AVB)           // 36864
#define ASMEM (2*ASTG)            // 73728

__global__ void __launch_bounds__(128, 3)
attn_tf32()
{
    extern __shared__ char smem[];
    const uint32_t sb = smem_u32(smem);

    const int qt  = 31 - (int)blockIdx.x;   // big causal tiles first
    const int h   = blockIdx.y;
    const int b   = blockIdx.z;
    const int tid  = threadIdx.x;
    const int warp = tid >> 5;
    const int lane = tid & 31;
    const int gid  = lane >> 2;
    const int tig  = lane & 3;

    const float* Qg = g_q + (size_t)(b*NH + h) * TT * DK;
    const float* Kg = g_k + (size_t)(b*NH + h) * TT * DK;
    const float* Vg = g_v + (size_t)(b*NH + h) * DK * TT;   // (d, packed-t)

    // Q fragments (scaled by 1/8 — exact on tf32-exact values)
    unsigned qf[8][4];
    {
        const int r0 = qt*64 + warp*16 + gid;
        #pragma unroll
        for (int ks = 0; ks < 8; ks++) {
            qf[ks][0] = tf32r(Qg[(size_t)r0*DK     + ks*8 + tig]     * 0.125f);
            qf[ks][1] = tf32r(Qg[(size_t)(r0+8)*DK + ks*8 + tig]     * 0.125f);
            qf[ks][2] = tf32r(Qg[(size_t)r0*DK     + ks*8 + tig + 4] * 0.125f);
            qf[ks][3] = tf32r(Qg[(size_t)(r0+8)*DK + ks*8 + tig + 4] * 0.125f);
        }
    }

    float o[8][4];
    #pragma unroll
    for (int nt = 0; nt < 8; nt++)
        #pragma unroll
        for (int c = 0; c < 4; c++) o[nt][c] = 0.f;
    float m0r = -1e30f, m1r = -1e30f, l0 = 0.f, l1 = 0.f;

    const int prow0 = warp*16 + gid;
    const int prow1 = prow0 + 8;

    // K tile: 64 rows t x 64 packed-d.  V tile: 64 rows d x 64 packed-t cols.
    auto load_kv = [&](int kt, int st) {
        const uint32_t sK = sb + st * ASTG;
        const uint32_t sV = sK + AKB;
        #pragma unroll
        for (int it = 0; it < 8; it++) {
            int lin = tid + it * 128;
            int row = lin >> 4, ch = lin & 15;
            cpasync16(sK + row*288 + ch*16, Kg + (size_t)(kt*64 + row)*DK + ch*4);
            cpasync16(sV + row*288 + ch*16, Vg + (size_t)row*TT + kt*64 + ch*4);
        }
        CP_COMMIT();
    };

    load_kv(0, 0);

    for (int kt = 0; kt <= qt; kt++) {
        __syncthreads();                         // other stage free (incl. its P use)
        if (kt < qt) { load_kv(kt + 1, (kt + 1) & 1); CP_WAIT(1); }
        else         { CP_WAIT(0); }
        __syncthreads();                         // stage kt visible

        const unsigned* Ks = (const unsigned*)(smem + (kt & 1) * ASTG);
        const unsigned* Vs = (const unsigned*)(smem + (kt & 1) * ASTG + AKB);
        unsigned* Ps = (unsigned*)(smem + (kt & 1) * ASTG);   // overlays K after S

        // S = Q K^T : 16x64 per warp; B-frag pair via one LDS.64
        float s[8][4];
        #pragma unroll
        for (int nt = 0; nt < 8; nt++)
            #pragma unroll
            for (int c = 0; c < 4; c++) s[nt][c] = 0.f;

        #pragma unroll
        for (int ks = 0; ks < 8; ks++) {
            #pragma unroll
            for (int nt = 0; nt < 8; nt++) {
                int tr = nt*8 + gid;
                uint2 bf2 = *(const uint2*)&Ks[tr*72 + ks*8 + 2*tig];
                unsigned bf[2] = { bf2.x, bf2.y };
                mma8(s[nt], qf[ks], bf);
            }
        }

        __syncthreads();       // ALL warps done reading K before P overwrites it

        if (kt == qt) {
            const int r0l = warp*16 + gid;
            #pragma unroll
            for (int nt = 0; nt < 8; nt++) {
                int col = nt*8 + 2*tig;
                if (col     > r0l)     s[nt][0] = -1e30f;
                if (col + 1 > r0l)     s[nt][1] = -1e30f;
                if (col     > r0l + 8) s[nt][2] = -1e30f;
                if (col + 1 > r0l + 8) s[nt][3] = -1e30f;
            }
        }

        // online softmax
        float mx0 = -1e30f, mx1 = -1e30f;
        #pragma unroll
        for (int nt = 0; nt < 8; nt++) {
            mx0 = fmaxf(mx0, fmaxf(s[nt][0], s[nt][1]));
            mx1 = fmaxf(mx1, fmaxf(s[nt][2], s[nt][3]));
        }
        mx0 = fmaxf(mx0, __shfl_xor_sync(0xffffffffu, mx0, 1));
        mx0 = fmaxf(mx0, __shfl_xor_sync(0xffffffffu, mx0, 2));
        mx1 = fmaxf(mx1, __shfl_xor_sync(0xffffffffu, mx1, 1));
        mx1 = fmaxf(mx1, __shfl_xor_sync(0xffffffffu, mx1, 2));

        float nm0 = fmaxf(m0r, mx0), nm1 = fmaxf(m1r, mx1);
        float corr0 = __expf(m0r - nm0), corr1 = __expf(m1r - nm1);
        float rs0 = 0.f, rs1 = 0.f;
        #pragma unroll
        for (int nt = 0; nt < 8; nt++) {
            s[nt][0] = __expf(s[nt][0] - nm0);
            s[nt][1] = __expf(s[nt][1] - nm0);
            s[nt][2] = __expf(s[nt][2] - nm1);
            s[nt][3] = __expf(s[nt][3] - nm1);
            rs0 += s[nt][0] + s[nt][1];
            rs1 += s[nt][2] + s[nt][3];
        }
        rs0 += __shfl_xor_sync(0xffffffffu, rs0, 1);
        rs0 += __shfl_xor_sync(0xffffffffu, rs0, 2);
        rs1 += __shfl_xor_sync(0xffffffffu, rs1, 1);
        rs1 += __shfl_xor_sync(0xffffffffu, rs1, 2);
        l0 = l0 * corr0 + rs0;  m0r = nm0;
        l1 = l1 * corr1 + rs1;  m1r = nm1;
        #pragma unroll
        for (int nt = 0; nt < 8; nt++) {
            o[nt][0] *= corr0;  o[nt][1] *= corr0;
            o[nt][2] *= corr1;  o[nt][3] *= corr1;
        }

        // stage P (tf32) into this warp's private 16-row band of the dead K region
        #pragma unroll
        for (int nt = 0; nt < 8; nt++) {
            uint2 p0; p0.x = tf32r(s[nt][0]); p0.y = tf32r(s[nt][1]);
            uint2 p1; p1.x = tf32r(s[nt][2]); p1.y = tf32r(s[nt][3]);
            *(uint2*)&Ps[prow0*68 + nt*8 + 2*tig] = p0;
            *(uint2*)&Ps[prow1*68 + nt*8 + 2*tig] = p1;
        }
        __syncwarp();

        // O += P V : B-frag pair via one LDS.64 (transposed+packed V)
        #pragma unroll
        for (int ks = 0; ks < 8; ks++) {
            unsigned pa[4];
            pa[0] = Ps[prow0*68 + ks*8 + tig];
            pa[1] = Ps[prow1*68 + ks*8 + tig];
            pa[2] = Ps[prow0*68 + ks*8 + tig + 4];
            pa[3] = Ps[prow1*68 + ks*8 + tig + 4];
            #pragma unroll
            for (int nt = 0; nt < 8; nt++) {
                uint2 vb2 = *(const uint2*)&Vs[(nt*8 + gid)*72 + ks*8 + 2*tig];
                unsigned vb[2] = { vb2.x, vb2.y };
                mma8(o[nt], pa, vb);
            }
        }
    }

    // epilogue: ctx (tf32-rounded so the Wo GEMM can consume raw bits)
    const float inv0 = 1.f / l0, inv1 = 1.f / l1;
    const int grow0 = b*TT + qt*64 + warp*16 + gid;
    #pragma unroll
    for (int nt = 0; nt < 8; nt++) {
        int dd = h*DK + nt*8 + 2*tig;
        float2 w0; w0.x = tf32rf(o[nt][0]*inv0); w0.y = tf32rf(o[nt][1]*inv0);
        float2 w1; w1.x = tf32rf(o[nt][2]*inv1); w1.y = tf32rf(o[nt][3]*inv1);
        *(float2*)&g_ctx[(size_t)grow0*DMODEL + dd]     = w0;
        *(float2*)&g_ctx[(size_t)(grow0+8)*DMODEL + dd] = w1;
    }
}

// ---------------------------------------------------------------------------

extern "C" void kernel_launch(void* const* d_in, const int* in_sizes, int n_in,
                              void* d_out, int out_size)
{
    const float* q  = (const float*)d_in[0];
    // d_in[1] = mask (causal by construction; applied analytically)
    const float* Wq = (const float*)d_in[2];
    const float* bq = (const float*)d_in[3];
    const float* Wk = (const float*)d_in[4];
    const float* bk = (const float*)d_in[5];
    const float* Wv = (const float*)d_in[6];
    const float* bv = (const float*)d_in[7];
    const float* Wo = (const float*)d_in[8];
    const float* bo = (const float*)d_in[9];
    float* out = (float*)d_out;

    // 0) pre-round operands to tf32 (rna)
    round_w_kernel<<<1024, 256>>>(Wq, Wk, Wv, Wo);
    round_q_kernel<<<8192, 256>>>(q);

    // 1) fused QKV projection (K packed-d, V transposed+packed-t)
    cudaFuncSetAttribute(gemm_mma<0>, cudaFuncAttributeMaxDynamicSharedMemorySize, GSMEM);
    gemm_mma<0><<<dim3(24, 64), 128, GSMEM>>>(bq, bk, bv, bo, nullptr);

    // 2) causal flash attention (P overlays dead K region -> 3 blocks/SM)
    cudaFuncSetAttribute(attn_tf32, cudaFuncAttributeMaxDynamicSharedMemorySize, ASMEM);
    attn_tf32<<<dim3(32, NH, BB), 128, ASMEM>>>();

    // 3) output projection
    cudaFuncSetAttribute(gemm_mma<1>, cudaFuncAttributeMaxDynamicSharedMemorySize, GSMEM);
    gemm_mma<1><<<dim3(8, 64), 128, GSMEM>>>(bq, bk, bv, bo, out);
}